// round 9
// baseline (speedup 1.0000x reference)
#include <cuda_runtime.h>
#include <cuda_bf16.h>
#include <cuda_fp16.h>
#include <math.h>
#include <stdint.h>

// Problem constants
#define NROWS 16384
#define DIN   1024
#define DEMB  256
#define KCB   1024
#define ALPHA 0.01f
#define EPSV  1e-5f
#define MARGIN 4.0f

// Output layout (float32, tuple order concatenated)
#define OFF_X        ((size_t)0)
#define OFF_CODES    ((size_t)16777216)
#define OFF_EMB      ((size_t)16793600)
#define OFF_COMMIT   ((size_t)16793601)
#define OFF_ENT      ((size_t)16793602)
#define OFF_EMA_VECS ((size_t)16793603)
#define OFF_EMA_SIZE ((size_t)17055747)
#define OFF_WEIGHT   ((size_t)17056771)

// ---------------------------------------------------------------------------
// Scratch (device globals; no allocations allowed)
__device__ float g_z[NROWS * DEMB];
__device__ float g_sqr[KCB];
__device__ int   g_codes[NROWS];
__device__ float g_dmin[NROWS];
__device__ float g_upd[KCB * DEMB];
__device__ float g_cnt[KCB];
__device__ float g_loss;
__device__ float g_size[KCB];
__device__ float g_Y[KCB * DIN];
__device__ __half g_dist[NROWS * KCB];        // 32 MB approx distances (fp16)
__device__ float g_wsT_hi[DEMB * DIN], g_wsT_lo[DEMB * DIN];
__device__ float g_wrT_hi[DIN * DEMB], g_wrT_lo[DIN * DEMB];
__device__ __nv_bfloat16 g_zh[NROWS * DEMB];
__device__ __nv_bfloat16 g_cbh[KCB * DEMB];

// ---------------------------------------------------------------------------
__device__ __forceinline__ uint32_t smem_u32(const void* p) {
    uint32_t a;
    asm("{ .reg .u64 t; cvta.to.shared.u64 t, %1; cvt.u32.u64 %0, t; }" : "=r"(a) : "l"(p));
    return a;
}
__device__ __forceinline__ void ldsm4(uint32_t* r, uint32_t addr) {
    asm volatile("ldmatrix.sync.aligned.m8n8.x4.shared.b16 {%0,%1,%2,%3}, [%4];"
                 : "=r"(r[0]), "=r"(r[1]), "=r"(r[2]), "=r"(r[3]) : "r"(addr));
}
__device__ __forceinline__ void mma_tf32(float* c, const uint32_t* a, const uint32_t* b) {
    asm volatile("mma.sync.aligned.m16n8k8.row.col.f32.tf32.tf32.f32 "
                 "{%0,%1,%2,%3}, {%4,%5,%6,%7}, {%8,%9}, {%0,%1,%2,%3};"
                 : "+f"(c[0]), "+f"(c[1]), "+f"(c[2]), "+f"(c[3])
                 : "r"(a[0]), "r"(a[1]), "r"(a[2]), "r"(a[3]), "r"(b[0]), "r"(b[1]));
}
__device__ __forceinline__ void mma_bf16(float* c, const uint32_t* a, const uint32_t* b) {
    asm volatile("mma.sync.aligned.m16n8k16.row.col.f32.bf16.bf16.f32 "
                 "{%0,%1,%2,%3}, {%4,%5,%6,%7}, {%8,%9}, {%0,%1,%2,%3};"
                 : "+f"(c[0]), "+f"(c[1]), "+f"(c[2]), "+f"(c[3])
                 : "r"(a[0]), "r"(a[1]), "r"(a[2]), "r"(a[3]), "r"(b[0]), "r"(b[1]));
}
__device__ __forceinline__ uint32_t f2tf32(float x) {
    uint32_t r;
    asm("cvt.rna.tf32.f32 %0, %1;" : "=r"(r) : "f"(x));
    return r;
}
#define CP16(sm, gp) asm volatile("cp.async.ca.shared.global [%0], [%1], 16;" :: "r"(sm), "l"(gp))
#define CPCOMMIT()   asm volatile("cp.async.commit_group;" ::: "memory")
#define CPWAIT0()    asm volatile("cp.async.wait_group 0;" ::: "memory")
#define CPWAIT1()    asm volatile("cp.async.wait_group 1;" ::: "memory")

// ===========================================================================
// 3xTF32 GEMM: C = A @ B^T + bias. A fp32 (split in-register), B pre-split.
// CTA 128x128, BK=32, cp.async 2-stage. 8 warps 4(m)x2(n), warp 32x64.
// B fragments loaded per-np inside the step loop -> live regs ~110 (no spills
// at the launch_bounds(256,2) 128-reg cap).
#define ZSTRIDE 36
#define ZARR (128 * ZSTRIDE)          // floats per array
#define ZSTAGE (3 * ZARR)
#define ZSMEM_BYTES (2 * ZSTAGE * 4)  // 110592

__device__ __forceinline__ void z_loads(uint32_t sbase, int buf,
    const float* __restrict__ A, const float* __restrict__ Bh,
    const float* __restrict__ Bl, int row0, int col0, int kdim, int kc, int tid)
{
    #pragma unroll
    for (int t = 0; t < 4; t++) {
        int seg = tid + t * 256;
        int rr = seg >> 3, cc = (seg & 7) * 4;
        uint32_t so = sbase + (uint32_t)(buf * ZSTAGE + rr * ZSTRIDE + cc) * 4u;
        CP16(so,                  A  + (size_t)(row0 + rr) * kdim + kc + cc);
        CP16(so + ZARR * 4u,      Bh + (size_t)(col0 + rr) * kdim + kc + cc);
        CP16(so + 2u * ZARR * 4u, Bl + (size_t)(col0 + rr) * kdim + kc + cc);
    }
    CPCOMMIT();
}

__global__ __launch_bounds__(256, 2) void k_tgemm32(
    const float* __restrict__ A,
    const float* __restrict__ Bh, const float* __restrict__ Bl,
    const float* __restrict__ bias, float* __restrict__ C,
    __nv_bfloat16* __restrict__ Chi, int ldc, int kdim, int write_bf)
{
    extern __shared__ float dsm[];
    const int tid = threadIdx.x, lane = tid & 31, wid = tid >> 5;
    const int warp_m = wid & 3, warp_n = wid >> 2;
    const int row0 = blockIdx.y * 128, col0 = blockIdx.x * 128;
    const int frow = lane & 15, fcol = (lane >> 4) * 4;
    const uint32_t sbase = smem_u32(dsm);

    float acc[2][8][4];
    #pragma unroll
    for (int a = 0; a < 2; a++)
        #pragma unroll
        for (int b = 0; b < 8; b++)
            #pragma unroll
            for (int c = 0; c < 4; c++) acc[a][b][c] = 0.0f;

    const int nch = kdim >> 5;
    z_loads(sbase, 0, A, Bh, Bl, row0, col0, kdim, 0, tid);

    for (int c = 0; c < nch; c++) {
        if (c + 1 < nch) {
            z_loads(sbase, (c + 1) & 1, A, Bh, Bl, row0, col0, kdim, (c + 1) * 32, tid);
            CPWAIT1();
        } else {
            CPWAIT0();
        }
        __syncthreads();
        const uint32_t sb = sbase + (uint32_t)((c & 1) * ZSTAGE) * 4u;
        #pragma unroll
        for (int s = 0; s < 4; s++) {
            const int k0 = s * 8;
            uint32_t ahi[2][4], alo[2][4];
            #pragma unroll
            for (int mt = 0; mt < 2; mt++) {
                uint32_t raw[4];
                ldsm4(raw, sb + (uint32_t)(((warp_m * 32 + mt * 16 + frow) * ZSTRIDE)
                                           + k0 + fcol) * 4u);
                #pragma unroll
                for (int q = 0; q < 4; q++) {
                    float x = __uint_as_float(raw[q]);
                    ahi[mt][q] = f2tf32(x);
                    alo[mt][q] = f2tf32(x - __uint_as_float(ahi[mt][q]));
                }
            }
            // B fragments per-np (short liveness): fcol-style addressing ->
            // n-group g uses regs {g, g+2}  (R5/R8-validated)
            #pragma unroll
            for (int np = 0; np < 4; np++) {
                uint32_t bh[4], bl[4];
                uint32_t off = (uint32_t)(((warp_n * 64 + np * 16 + frow) * ZSTRIDE)
                                          + k0 + fcol) * 4u;
                ldsm4(bh, sb + ZARR * 4u + off);
                ldsm4(bl, sb + 2u * ZARR * 4u + off);
                #pragma unroll
                for (int mt = 0; mt < 2; mt++)
                    #pragma unroll
                    for (int g = 0; g < 2; g++) {
                        const int nt = np * 2 + g;
                        uint32_t vh[2] = {bh[g], bh[g + 2]};
                        uint32_t vl[2] = {bl[g], bl[g + 2]};
                        mma_tf32(acc[mt][nt], ahi[mt], vh);
                        mma_tf32(acc[mt][nt], ahi[mt], vl);
                        mma_tf32(acc[mt][nt], alo[mt], vh);
                    }
            }
        }
        __syncthreads();
    }

    const int tr = lane >> 2, tc = (lane & 3) * 2;
    #pragma unroll
    for (int mt = 0; mt < 2; mt++)
        #pragma unroll
        for (int h = 0; h < 2; h++) {
            int row = row0 + warp_m * 32 + mt * 16 + h * 8 + tr;
            #pragma unroll
            for (int nt = 0; nt < 8; nt++) {
                int col = col0 + warp_n * 64 + nt * 8 + tc;
                float v0 = acc[mt][nt][h * 2 + 0] + bias[col];
                float v1 = acc[mt][nt][h * 2 + 1] + bias[col + 1];
                size_t o = (size_t)row * ldc + col;
                *reinterpret_cast<float2*>(C + o) = make_float2(v0, v1);
                if (write_bf) {
                    __nv_bfloat162 hp = __floats2bfloat162_rn(v0, v1);
                    *reinterpret_cast<uint32_t*>(Chi + o) = *reinterpret_cast<uint32_t*>(&hp);
                }
            }
        }
}

// ===========================================================================
// dist = sqr - 2 * (zh @ cbh^T), single bf16 product, fp16 output (32 MB).
// CTA 128x128, BK=32, cp.async 2-stage. 8 warps 4x2, warp 32x64, m16n8k16.
#define CSTRIDE 40
#define CARR (128 * CSTRIDE)   // bf16 units

__device__ __forceinline__ void cov_loads(uint32_t sbase, int buf,
                                          int row0, int code0, int kc, int tid)
{
    #pragma unroll
    for (int t = 0; t < 2; t++) {
        int seg = tid + t * 256;
        int rr = seg >> 2, cc = (seg & 3) * 8;
        uint32_t so = sbase + (uint32_t)(buf * 2 * CARR + rr * CSTRIDE + cc) * 2u;
        CP16(so,             g_zh  + (size_t)(row0 + rr) * DEMB + kc + cc);
        CP16(so + CARR * 2u, g_cbh + (size_t)(code0 + rr) * DEMB + kc + cc);
    }
    CPCOMMIT();
}

__global__ __launch_bounds__(256, 2) void k_cov()
{
    __shared__ __align__(16) __nv_bfloat16 sm[2][2][CARR];   // 40 KB
    __shared__ float s_sqr[128];
    const int tid = threadIdx.x, lane = tid & 31, wid = tid >> 5;
    const int warp_m = wid & 3, warp_n = wid >> 2;
    const int row0 = blockIdx.y * 128, code0 = blockIdx.x * 128;
    const uint32_t sbase = smem_u32(&sm[0][0][0]);
    const int quad = lane >> 3;

    if (tid < 128) s_sqr[tid] = g_sqr[code0 + tid];

    float acc[2][8][4];
    #pragma unroll
    for (int a = 0; a < 2; a++)
        #pragma unroll
        for (int b = 0; b < 8; b++)
            #pragma unroll
            for (int c = 0; c < 4; c++) acc[a][b][c] = 0.0f;

    cov_loads(sbase, 0, row0, code0, 0, tid);
    const int nch = DEMB >> 5;   // 8
    for (int c = 0; c < nch; c++) {
        if (c + 1 < nch) { cov_loads(sbase, (c + 1) & 1, row0, code0, (c + 1) * 32, tid); CPWAIT1(); }
        else CPWAIT0();
        __syncthreads();
        const uint32_t sb = sbase + (uint32_t)((c & 1) * 2 * CARR) * 2u;
        #pragma unroll
        for (int ks = 0; ks < 2; ks++) {
            const int k0 = ks * 16;
            uint32_t a[2][4];
            #pragma unroll
            for (int mt = 0; mt < 2; mt++)
                ldsm4(a[mt], sb + (uint32_t)(((warp_m * 32 + mt * 16 + (lane & 15)) * CSTRIDE)
                                             + k0 + (lane >> 4) * 8) * 2u);
            // quad-style addressing: n-group g uses CONSECUTIVE regs {2g, 2g+1}
            // (R6/R8-validated)
            #pragma unroll
            for (int np = 0; np < 4; np++) {
                uint32_t b[4];
                ldsm4(b, sb + CARR * 2u +
                      (uint32_t)(((warp_n * 64 + np * 16 + (quad >> 1) * 8 + (lane & 7)) * CSTRIDE)
                                 + k0 + (quad & 1) * 8) * 2u);
                #pragma unroll
                for (int mt = 0; mt < 2; mt++)
                    #pragma unroll
                    for (int g = 0; g < 2; g++) {
                        uint32_t vb[2] = {b[g * 2], b[g * 2 + 1]};
                        mma_bf16(acc[mt][np * 2 + g], a[mt], vb);
                    }
            }
        }
        __syncthreads();
    }

    const int tr = lane >> 2, tc = (lane & 3) * 2;
    #pragma unroll
    for (int mt = 0; mt < 2; mt++)
        #pragma unroll
        for (int h = 0; h < 2; h++) {
            int row = row0 + warp_m * 32 + mt * 16 + h * 8 + tr;
            #pragma unroll
            for (int nt = 0; nt < 8; nt++) {
                int colL = warp_n * 64 + nt * 8 + tc;
                float d0 = fmaf(-2.0f, acc[mt][nt][h * 2 + 0], s_sqr[colL]);
                float d1 = fmaf(-2.0f, acc[mt][nt][h * 2 + 1], s_sqr[colL + 1]);
                __half2 hd;
                hd.x = __float2half_rn(d0);
                hd.y = __float2half_rn(d1);
                *reinterpret_cast<__half2*>(g_dist + (size_t)row * KCB + code0 + colL) = hd;
            }
        }
}

// ===========================================================================
// Refine + fused scatter: approx min from g_dist (fp16), exact fp32 distances
// for candidates, winner; then segment-sum z into g_upd, counts, loss.
__global__ __launch_bounds__(256) void k_refine(
    const float* __restrict__ cb, float* __restrict__ out)
{
    __shared__ float s_z[DEMB];
    __shared__ float s_red[256];
    __shared__ int   s_cand[64];
    __shared__ int   s_ncand;
    __shared__ unsigned long long s_best;

    const int row = blockIdx.x;
    const int t = threadIdx.x;
    const int wid = t >> 5, lane = t & 31;

    float zval = g_z[(size_t)row * DEMB + t];
    s_z[t] = zval;
    if (t == 0) { s_ncand = 0; s_best = 0xFFFFFFFFFFFFFFFFull; }

    const __half2* drow = reinterpret_cast<const __half2*>(g_dist + (size_t)row * KCB);
    __half2 p0 = drow[t];          // codes 2t, 2t+1
    __half2 p1 = drow[256 + t];    // codes 512+2t, 512+2t+1
    float dt[4];
    int   ci[4];
    dt[0] = __half2float(p0.x); ci[0] = 2 * t;
    dt[1] = __half2float(p0.y); ci[1] = 2 * t + 1;
    dt[2] = __half2float(p1.x); ci[2] = 512 + 2 * t;
    dt[3] = __half2float(p1.y); ci[3] = 512 + 2 * t + 1;
    float lm = fminf(fminf(dt[0], dt[1]), fminf(dt[2], dt[3]));

    s_red[t] = lm;
    __syncthreads();
    for (int s = 128; s > 0; s >>= 1) {
        if (t < s) s_red[t] = fminf(s_red[t], s_red[t + s]);
        __syncthreads();
    }
    const float thr = s_red[0] + MARGIN;
    __syncthreads();

    #pragma unroll
    for (int i = 0; i < 4; i++) {
        if (dt[i] <= thr) {
            int idx = atomicAdd(&s_ncand, 1);
            if (idx < 64) s_cand[idx] = ci[i];
        }
    }
    __syncthreads();
    const int nc = s_ncand;

    if (nc <= 64) {
        for (int cc = wid; cc < nc; cc += 8) {
            int c = s_cand[cc];
            const float* cbr = cb + (size_t)c * DEMB;
            float dot = 0.0f;
            #pragma unroll
            for (int j = 0; j < 8; j++) dot = fmaf(s_z[lane + 32 * j], cbr[lane + 32 * j], dot);
            #pragma unroll
            for (int o = 16; o > 0; o >>= 1) dot += __shfl_xor_sync(0xffffffffu, dot, o);
            if (lane == 0) {
                float d = fmaf(-2.0f, dot, g_sqr[c]);
                unsigned u = __float_as_uint(d);
                u = (u & 0x80000000u) ? ~u : (u | 0x80000000u);
                atomicMin(&s_best, ((unsigned long long)u << 32) | (unsigned)c);
            }
        }
    } else {
        for (int c = wid; c < KCB; c += 8) {
            const float* cbr = cb + (size_t)c * DEMB;
            float dot = 0.0f;
            #pragma unroll
            for (int j = 0; j < 8; j++) dot = fmaf(s_z[lane + 32 * j], cbr[lane + 32 * j], dot);
            #pragma unroll
            for (int o = 16; o > 0; o >>= 1) dot += __shfl_xor_sync(0xffffffffu, dot, o);
            if (lane == 0) {
                float d = fmaf(-2.0f, dot, g_sqr[c]);
                unsigned u = __float_as_uint(d);
                u = (u & 0x80000000u) ? ~u : (u | 0x80000000u);
                atomicMin(&s_best, ((unsigned long long)u << 32) | (unsigned)c);
            }
        }
    }
    __syncthreads();

    // winner
    unsigned long long p = s_best;
    int code = (int)(unsigned)(p & 0xFFFFFFFFull);
    unsigned ue = (unsigned)(p >> 32);
    float dmin = (ue & 0x80000000u) ? __uint_as_float(ue & 0x7FFFFFFFu)
                                    : __uint_as_float(~ue);

    // fused scatter: segment-sum z, counts, loss
    atomicAdd(&g_upd[(size_t)code * DEMB + t], zval);
    float sq = zval * zval;
    #pragma unroll
    for (int o = 16; o > 0; o >>= 1) sq += __shfl_xor_sync(0xffffffffu, sq, o);
    if (lane == 0) s_red[wid] = sq;
    __syncthreads();
    if (t == 0) {
        float tot = 0.0f;
        #pragma unroll
        for (int w = 0; w < 8; w++) tot += s_red[w];
        g_codes[row] = code;
        g_dmin[row]  = dmin;
        out[OFF_CODES + row] = (float)code;
        atomicAdd(&g_loss, tot + dmin);
        atomicAdd(&g_cnt[code], 1.0f);
    }
}

// ===========================================================================
// transpose + tf32 hi/lo split
__global__ void k_trsplit(const float* __restrict__ src, float* __restrict__ hi,
                          float* __restrict__ lo, int R, int C) {
    int id = blockIdx.x * blockDim.x + threadIdx.x;
    int c = id / R, r = id - c * R;
    float v = src[(size_t)r * C + c];
    uint32_t h = f2tf32(v);
    float hf = __uint_as_float(h);
    hi[id] = hf;
    lo[id] = __uint_as_float(f2tf32(v - hf));
}

// codebook -> bf16 (hi only)
__global__ void k_convcb(const float* __restrict__ src, __nv_bfloat16* __restrict__ hi) {
    size_t i = ((size_t)blockIdx.x * blockDim.x + threadIdx.x) * 4;
    float4 v = *reinterpret_cast<const float4*>(src + i);
    __nv_bfloat162 h01 = __floats2bfloat162_rn(v.x, v.y);
    __nv_bfloat162 h23 = __floats2bfloat162_rn(v.z, v.w);
    uint2 hp;
    hp.x = *reinterpret_cast<uint32_t*>(&h01); hp.y = *reinterpret_cast<uint32_t*>(&h23);
    *reinterpret_cast<uint2*>(hi + i) = hp;
}

// ---------------------------------------------------------------------------
__global__ void k_init() {
    int i = blockIdx.x * blockDim.x + threadIdx.x;
    if (i < KCB * DEMB) g_upd[i] = 0.0f;
    if (i < KCB)        g_cnt[i] = 0.0f;
    if (i == 0)         g_loss  = 0.0f;
}

__global__ void k_sqr(const float* __restrict__ cb) {
    int k = blockIdx.x, j = threadIdx.x;
    float v = cb[k * DEMB + j];
    float s = v * v;
    #pragma unroll
    for (int o = 16; o > 0; o >>= 1) s += __shfl_xor_sync(0xffffffffu, s, o);
    __shared__ float wsum[8];
    if ((j & 31) == 0) wsum[j >> 5] = s;
    __syncthreads();
    if (j == 0) {
        float tot = 0.0f;
        #pragma unroll
        for (int w = 0; w < 8; w++) tot += wsum[w];
        g_sqr[k] = tot;
    }
}

__global__ __launch_bounds__(1024) void k_final_small(
    const float* __restrict__ ema_size_in, float* __restrict__ out)
{
    __shared__ float sh[1024];
    int t = threadIdx.x;
    float cnt = g_cnt[t];
    float esz = ema_size_in[t] + ALPHA * (cnt - ema_size_in[t]);
    out[OFF_EMA_SIZE + t] = esz;

    sh[t] = esz;
    __syncthreads();
    for (int s = 512; s > 0; s >>= 1) {
        if (t < s) sh[t] += sh[t + s];
        __syncthreads();
    }
    float n = sh[0];
    __syncthreads();

    float coef = n / (n + (float)KCB * EPSV);
    g_size[t]  = coef * (esz + EPSV);

    float p = cnt * (1.0f / (float)NROWS);
    float e = (cnt > 0.0f) ? (-p * logf(p)) : 0.0f;
    sh[t] = e;
    __syncthreads();
    for (int s = 512; s > 0; s >>= 1) {
        if (t < s) sh[t] += sh[t + s];
        __syncthreads();
    }
    if (t == 0) {
        out[OFF_ENT]    = sh[0] / logf(2.0f);
        out[OFF_EMB]    = g_loss;
        out[OFF_COMMIT] = g_loss;
    }
}

__global__ void k_ema(const float* __restrict__ ema_vecs_in, float* __restrict__ out) {
    int i = blockIdx.x * blockDim.x + threadIdx.x;
    float v = ema_vecs_in[i] + ALPHA * (g_upd[i] - ema_vecs_in[i]);
    out[OFF_EMA_VECS + i] = v;
    out[OFF_WEIGHT + i]   = v / g_size[i >> 8];
}

__global__ __launch_bounds__(256) void k_gather(float* __restrict__ out) {
    int row  = blockIdx.x;
    int code = g_codes[row];
    const float4* src = reinterpret_cast<const float4*>(g_Y + (size_t)code * DIN);
    float4* dst = reinterpret_cast<float4*>(out + OFF_X + (size_t)row * DIN);
    dst[threadIdx.x] = src[threadIdx.x];
}

// ---------------------------------------------------------------------------
extern "C" void kernel_launch(void* const* d_in, const int* in_sizes, int n_in,
                              void* d_out, int out_size) {
    const float* input    = (const float*)d_in[0];
    const float* W_send   = (const float*)d_in[1];
    const float* b_send   = (const float*)d_in[2];
    const float* W_recv   = (const float*)d_in[3];
    const float* b_recv   = (const float*)d_in[4];
    const float* codebook = (const float*)d_in[5];
    const float* ema_vecs = (const float*)d_in[6];
    const float* ema_size = (const float*)d_in[7];
    float* out = (float*)d_out;

    float *z_ptr, *Y_ptr, *wsh, *wsl, *wrh, *wrl;
    __nv_bfloat16 *zh, *cbh;
    cudaGetSymbolAddress((void**)&z_ptr, g_z);
    cudaGetSymbolAddress((void**)&Y_ptr, g_Y);
    cudaGetSymbolAddress((void**)&wsh, g_wsT_hi); cudaGetSymbolAddress((void**)&wsl, g_wsT_lo);
    cudaGetSymbolAddress((void**)&wrh, g_wrT_hi); cudaGetSymbolAddress((void**)&wrl, g_wrT_lo);
    cudaGetSymbolAddress((void**)&zh, g_zh);
    cudaGetSymbolAddress((void**)&cbh, g_cbh);

    cudaFuncSetAttribute(k_tgemm32, cudaFuncAttributeMaxDynamicSharedMemorySize, ZSMEM_BYTES);

    k_init<<<1024, 256>>>();                                              // 0
    k_trsplit<<<DIN * DEMB / 256, 256>>>(W_send, wsh, wsl, DIN, DEMB);    // 1
    k_trsplit<<<DIN * DEMB / 256, 256>>>(W_recv, wrh, wrl, DEMB, DIN);    // 2
    // z = input @ W_send + b_send (3xTF32, fused bf16-hi z output)       // 3 (profiled slot)
    k_tgemm32<<<dim3(2, 128), 256, ZSMEM_BYTES>>>(input, wsh, wsl, b_send,
                                                  z_ptr, zh, DEMB, DIN, 1);
    k_sqr<<<KCB, 256>>>(codebook);                                        // 4
    k_convcb<<<KCB * DEMB / 1024, 256>>>(codebook, cbh);                  // 5
    // Y = codebook @ W_recv + b_recv (3xTF32)                            // 6
    k_tgemm32<<<dim3(8, 8), 256, ZSMEM_BYTES>>>(codebook, wrh, wrl, b_recv,
                                                Y_ptr, (__nv_bfloat16*)nullptr,
                                                DIN, DEMB, 0);
    k_cov<<<dim3(8, 128), 256>>>();                                       // 7
    k_refine<<<NROWS, 256>>>(codebook, out);                              // 8 (fused scatter)
    k_final_small<<<1, 1024>>>(ema_size, out);                            // 9
    k_ema<<<1024, 256>>>(ema_vecs, out);                                  // 10
    k_gather<<<NROWS, 256>>>(out);                                        // 11
}

// round 10
// speedup vs baseline: 1.0001x; 1.0001x over previous
#include <cuda_runtime.h>
#include <cuda_bf16.h>
#include <cuda_fp16.h>
#include <math.h>
#include <stdint.h>

// Problem constants
#define NROWS 16384
#define DIN   1024
#define DEMB  256
#define KCB   1024
#define ALPHA 0.01f
#define EPSV  1e-5f
#define MARGIN 4.0f

// Output layout (float32, tuple order concatenated)
#define OFF_X        ((size_t)0)
#define OFF_CODES    ((size_t)16777216)
#define OFF_EMB      ((size_t)16793600)
#define OFF_COMMIT   ((size_t)16793601)
#define OFF_ENT      ((size_t)16793602)
#define OFF_EMA_VECS ((size_t)16793603)
#define OFF_EMA_SIZE ((size_t)17055747)
#define OFF_WEIGHT   ((size_t)17056771)

// ---------------------------------------------------------------------------
// Scratch (device globals; no allocations allowed)
__device__ float g_z[NROWS * DEMB];
__device__ float g_sqr[KCB];
__device__ int   g_codes[NROWS];
__device__ float g_dmin[NROWS];
__device__ float g_upd[KCB * DEMB];
__device__ float g_cnt[KCB];
__device__ float g_loss;
__device__ float g_size[KCB];
__device__ float g_Y[KCB * DIN];
__device__ __half g_dist[NROWS * KCB];        // 32 MB approx distances (fp16)
__device__ float g_wsT_hi[DEMB * DIN], g_wsT_lo[DEMB * DIN];
__device__ float g_wrT_hi[DIN * DEMB], g_wrT_lo[DIN * DEMB];
__device__ __nv_bfloat16 g_zh[NROWS * DEMB];
__device__ __nv_bfloat16 g_cbh[KCB * DEMB];

// ---------------------------------------------------------------------------
__device__ __forceinline__ uint32_t smem_u32(const void* p) {
    uint32_t a;
    asm("{ .reg .u64 t; cvta.to.shared.u64 t, %1; cvt.u32.u64 %0, t; }" : "=r"(a) : "l"(p));
    return a;
}
__device__ __forceinline__ void ldsm4(uint32_t* r, uint32_t addr) {
    asm volatile("ldmatrix.sync.aligned.m8n8.x4.shared.b16 {%0,%1,%2,%3}, [%4];"
                 : "=r"(r[0]), "=r"(r[1]), "=r"(r[2]), "=r"(r[3]) : "r"(addr));
}
__device__ __forceinline__ void mma_tf32(float* c, const uint32_t* a, const uint32_t* b) {
    asm volatile("mma.sync.aligned.m16n8k8.row.col.f32.tf32.tf32.f32 "
                 "{%0,%1,%2,%3}, {%4,%5,%6,%7}, {%8,%9}, {%0,%1,%2,%3};"
                 : "+f"(c[0]), "+f"(c[1]), "+f"(c[2]), "+f"(c[3])
                 : "r"(a[0]), "r"(a[1]), "r"(a[2]), "r"(a[3]), "r"(b[0]), "r"(b[1]));
}
__device__ __forceinline__ void mma_bf16(float* c, const uint32_t* a, const uint32_t* b) {
    asm volatile("mma.sync.aligned.m16n8k16.row.col.f32.bf16.bf16.f32 "
                 "{%0,%1,%2,%3}, {%4,%5,%6,%7}, {%8,%9}, {%0,%1,%2,%3};"
                 : "+f"(c[0]), "+f"(c[1]), "+f"(c[2]), "+f"(c[3])
                 : "r"(a[0]), "r"(a[1]), "r"(a[2]), "r"(a[3]), "r"(b[0]), "r"(b[1]));
}
__device__ __forceinline__ uint32_t f2tf32(float x) {
    uint32_t r;
    asm("cvt.rna.tf32.f32 %0, %1;" : "=r"(r) : "f"(x));
    return r;
}
#define CP16(sm, gp) asm volatile("cp.async.ca.shared.global [%0], [%1], 16;" :: "r"(sm), "l"(gp))
#define CPCOMMIT()   asm volatile("cp.async.commit_group;" ::: "memory")
#define CPWAIT0()    asm volatile("cp.async.wait_group 0;" ::: "memory")
#define CPWAIT1()    asm volatile("cp.async.wait_group 1;" ::: "memory")

// ===========================================================================
// 3xTF32 GEMM: C = A @ B^T + bias. A fp32 (split in-register), B pre-split.
// CTA tile 128(M) x 64(N), BK=32, cp.async 2-stage. 8 warps 4(m)x2(n),
// warp tile 32x32 (acc = 32 regs). 3 CTAs/SM (72 KB smem, regs <= 85)
// -> 24 warps/SM to hide the mma accumulate-chain latency.
#define ZSTRIDE 36
#define AARR (128 * ZSTRIDE)          // A floats per stage
#define BARR (64 * ZSTRIDE)           // B floats per stage (per array)
#define ZSTAGE (AARR + 2 * BARR)      // 9216 floats
#define ZSMEM_BYTES (2 * ZSTAGE * 4)  // 73728

__device__ __forceinline__ void z_loads(uint32_t sbase, int buf,
    const float* __restrict__ A, const float* __restrict__ Bh,
    const float* __restrict__ Bl, int row0, int col0, int kdim, int kc, int tid)
{
    // A: 128 x 32 (1024 float4)
    #pragma unroll
    for (int i = 0; i < 4; i++) {
        int seg = tid + i * 256;
        int rr = seg >> 3, cc = (seg & 7) * 4;
        CP16(sbase + (uint32_t)(buf * ZSTAGE + rr * ZSTRIDE + cc) * 4u,
             A + (size_t)(row0 + rr) * kdim + kc + cc);
    }
    // Bh, Bl: 64 x 32 each (512 float4 each)
    #pragma unroll
    for (int i = 0; i < 2; i++) {
        int seg = tid + i * 256;
        int rr = seg >> 3, cc = (seg & 7) * 4;
        uint32_t so = sbase + (uint32_t)(buf * ZSTAGE + AARR + rr * ZSTRIDE + cc) * 4u;
        CP16(so,              Bh + (size_t)(col0 + rr) * kdim + kc + cc);
        CP16(so + BARR * 4u,  Bl + (size_t)(col0 + rr) * kdim + kc + cc);
    }
    CPCOMMIT();
}

__global__ __launch_bounds__(256, 3) void k_tgemm32(
    const float* __restrict__ A,
    const float* __restrict__ Bh, const float* __restrict__ Bl,
    const float* __restrict__ bias, float* __restrict__ C,
    __nv_bfloat16* __restrict__ Chi, int ldc, int kdim, int write_bf)
{
    extern __shared__ float dsm[];
    const int tid = threadIdx.x, lane = tid & 31, wid = tid >> 5;
    const int warp_m = wid & 3, warp_n = wid >> 2;   // 4 x 2
    const int row0 = blockIdx.y * 128, col0 = blockIdx.x * 64;
    const int frow = lane & 15, fcol = (lane >> 4) * 4;
    const uint32_t sbase = smem_u32(dsm);

    float acc[2][4][4];
    #pragma unroll
    for (int a = 0; a < 2; a++)
        #pragma unroll
        for (int b = 0; b < 4; b++)
            #pragma unroll
            for (int c = 0; c < 4; c++) acc[a][b][c] = 0.0f;

    const int nch = kdim >> 5;
    z_loads(sbase, 0, A, Bh, Bl, row0, col0, kdim, 0, tid);

    for (int c = 0; c < nch; c++) {
        if (c + 1 < nch) {
            z_loads(sbase, (c + 1) & 1, A, Bh, Bl, row0, col0, kdim, (c + 1) * 32, tid);
            CPWAIT1();
        } else {
            CPWAIT0();
        }
        __syncthreads();
        const uint32_t sb = sbase + (uint32_t)((c & 1) * ZSTAGE) * 4u;
        #pragma unroll
        for (int s = 0; s < 4; s++) {
            const int k0 = s * 8;
            uint32_t ahi[2][4], alo[2][4];
            #pragma unroll
            for (int mt = 0; mt < 2; mt++) {
                uint32_t raw[4];
                ldsm4(raw, sb + (uint32_t)(((warp_m * 32 + mt * 16 + frow) * ZSTRIDE)
                                           + k0 + fcol) * 4u);
                #pragma unroll
                for (int q = 0; q < 4; q++) {
                    float x = __uint_as_float(raw[q]);
                    ahi[mt][q] = f2tf32(x);
                    alo[mt][q] = f2tf32(x - __uint_as_float(ahi[mt][q]));
                }
            }
            // B per-np (short liveness). fcol-style addressing ->
            // n-group g uses regs {g, g+2}  (R5/R8/R9-validated)
            #pragma unroll
            for (int np = 0; np < 2; np++) {
                uint32_t bh[4], bl[4];
                uint32_t off = (uint32_t)(((warp_n * 32 + np * 16 + frow) * ZSTRIDE)
                                          + k0 + fcol) * 4u;
                ldsm4(bh, sb + AARR * 4u + off);
                ldsm4(bl, sb + (AARR + BARR) * 4u + off);
                #pragma unroll
                for (int mt = 0; mt < 2; mt++)
                    #pragma unroll
                    for (int g = 0; g < 2; g++) {
                        const int nt = np * 2 + g;
                        uint32_t vh[2] = {bh[g], bh[g + 2]};
                        uint32_t vl[2] = {bl[g], bl[g + 2]};
                        mma_tf32(acc[mt][nt], ahi[mt], vh);
                        mma_tf32(acc[mt][nt], ahi[mt], vl);
                        mma_tf32(acc[mt][nt], alo[mt], vh);
                    }
            }
        }
        __syncthreads();
    }

    const int tr = lane >> 2, tc = (lane & 3) * 2;
    #pragma unroll
    for (int mt = 0; mt < 2; mt++)
        #pragma unroll
        for (int h = 0; h < 2; h++) {
            int row = row0 + warp_m * 32 + mt * 16 + h * 8 + tr;
            #pragma unroll
            for (int nt = 0; nt < 4; nt++) {
                int col = col0 + warp_n * 32 + nt * 8 + tc;
                float v0 = acc[mt][nt][h * 2 + 0] + bias[col];
                float v1 = acc[mt][nt][h * 2 + 1] + bias[col + 1];
                size_t o = (size_t)row * ldc + col;
                *reinterpret_cast<float2*>(C + o) = make_float2(v0, v1);
                if (write_bf) {
                    __nv_bfloat162 hp = __floats2bfloat162_rn(v0, v1);
                    *reinterpret_cast<uint32_t*>(Chi + o) = *reinterpret_cast<uint32_t*>(&hp);
                }
            }
        }
}

// ===========================================================================
// dist = sqr - 2 * (zh @ cbh^T), single bf16 product, fp16 output (32 MB).
// CTA 128x128, BK=32, cp.async 2-stage. 8 warps 4x2, warp 32x64, m16n8k16.
#define CSTRIDE 40
#define CARR (128 * CSTRIDE)   // bf16 units

__device__ __forceinline__ void cov_loads(uint32_t sbase, int buf,
                                          int row0, int code0, int kc, int tid)
{
    #pragma unroll
    for (int t = 0; t < 2; t++) {
        int seg = tid + t * 256;
        int rr = seg >> 2, cc = (seg & 3) * 8;
        uint32_t so = sbase + (uint32_t)(buf * 2 * CARR + rr * CSTRIDE + cc) * 2u;
        CP16(so,             g_zh  + (size_t)(row0 + rr) * DEMB + kc + cc);
        CP16(so + CARR * 2u, g_cbh + (size_t)(code0 + rr) * DEMB + kc + cc);
    }
    CPCOMMIT();
}

__global__ __launch_bounds__(256, 2) void k_cov()
{
    __shared__ __align__(16) __nv_bfloat16 sm[2][2][CARR];   // 40 KB
    __shared__ float s_sqr[128];
    const int tid = threadIdx.x, lane = tid & 31, wid = tid >> 5;
    const int warp_m = wid & 3, warp_n = wid >> 2;
    const int row0 = blockIdx.y * 128, code0 = blockIdx.x * 128;
    const uint32_t sbase = smem_u32(&sm[0][0][0]);
    const int quad = lane >> 3;

    if (tid < 128) s_sqr[tid] = g_sqr[code0 + tid];

    float acc[2][8][4];
    #pragma unroll
    for (int a = 0; a < 2; a++)
        #pragma unroll
        for (int b = 0; b < 8; b++)
            #pragma unroll
            for (int c = 0; c < 4; c++) acc[a][b][c] = 0.0f;

    cov_loads(sbase, 0, row0, code0, 0, tid);
    const int nch = DEMB >> 5;   // 8
    for (int c = 0; c < nch; c++) {
        if (c + 1 < nch) { cov_loads(sbase, (c + 1) & 1, row0, code0, (c + 1) * 32, tid); CPWAIT1(); }
        else CPWAIT0();
        __syncthreads();
        const uint32_t sb = sbase + (uint32_t)((c & 1) * 2 * CARR) * 2u;
        #pragma unroll
        for (int ks = 0; ks < 2; ks++) {
            const int k0 = ks * 16;
            uint32_t a[2][4];
            #pragma unroll
            for (int mt = 0; mt < 2; mt++)
                ldsm4(a[mt], sb + (uint32_t)(((warp_m * 32 + mt * 16 + (lane & 15)) * CSTRIDE)
                                             + k0 + (lane >> 4) * 8) * 2u);
            // quad-style addressing: n-group g uses CONSECUTIVE regs {2g, 2g+1}
            // (R6/R8/R9-validated)
            #pragma unroll
            for (int np = 0; np < 4; np++) {
                uint32_t b[4];
                ldsm4(b, sb + CARR * 2u +
                      (uint32_t)(((warp_n * 64 + np * 16 + (quad >> 1) * 8 + (lane & 7)) * CSTRIDE)
                                 + k0 + (quad & 1) * 8) * 2u);
                #pragma unroll
                for (int mt = 0; mt < 2; mt++)
                    #pragma unroll
                    for (int g = 0; g < 2; g++) {
                        uint32_t vb[2] = {b[g * 2], b[g * 2 + 1]};
                        mma_bf16(acc[mt][np * 2 + g], a[mt], vb);
                    }
            }
        }
        __syncthreads();
    }

    const int tr = lane >> 2, tc = (lane & 3) * 2;
    #pragma unroll
    for (int mt = 0; mt < 2; mt++)
        #pragma unroll
        for (int h = 0; h < 2; h++) {
            int row = row0 + warp_m * 32 + mt * 16 + h * 8 + tr;
            #pragma unroll
            for (int nt = 0; nt < 8; nt++) {
                int colL = warp_n * 64 + nt * 8 + tc;
                float d0 = fmaf(-2.0f, acc[mt][nt][h * 2 + 0], s_sqr[colL]);
                float d1 = fmaf(-2.0f, acc[mt][nt][h * 2 + 1], s_sqr[colL + 1]);
                __half2 hd;
                hd.x = __float2half_rn(d0);
                hd.y = __float2half_rn(d1);
                *reinterpret_cast<__half2*>(g_dist + (size_t)row * KCB + code0 + colL) = hd;
            }
        }
}

// ===========================================================================
// Refine + fused scatter: approx min from g_dist (fp16), exact fp32 distances
// for candidates, winner; then segment-sum z into g_upd, counts, loss.
__global__ __launch_bounds__(256) void k_refine(
    const float* __restrict__ cb, float* __restrict__ out)
{
    __shared__ float s_z[DEMB];
    __shared__ float s_red[256];
    __shared__ int   s_cand[64];
    __shared__ int   s_ncand;
    __shared__ unsigned long long s_best;

    const int row = blockIdx.x;
    const int t = threadIdx.x;
    const int wid = t >> 5, lane = t & 31;

    float zval = g_z[(size_t)row * DEMB + t];
    s_z[t] = zval;
    if (t == 0) { s_ncand = 0; s_best = 0xFFFFFFFFFFFFFFFFull; }

    const __half2* drow = reinterpret_cast<const __half2*>(g_dist + (size_t)row * KCB);
    __half2 p0 = drow[t];          // codes 2t, 2t+1
    __half2 p1 = drow[256 + t];    // codes 512+2t, 512+2t+1
    float dt[4];
    int   ci[4];
    dt[0] = __half2float(p0.x); ci[0] = 2 * t;
    dt[1] = __half2float(p0.y); ci[1] = 2 * t + 1;
    dt[2] = __half2float(p1.x); ci[2] = 512 + 2 * t;
    dt[3] = __half2float(p1.y); ci[3] = 512 + 2 * t + 1;
    float lm = fminf(fminf(dt[0], dt[1]), fminf(dt[2], dt[3]));

    s_red[t] = lm;
    __syncthreads();
    for (int s = 128; s > 0; s >>= 1) {
        if (t < s) s_red[t] = fminf(s_red[t], s_red[t + s]);
        __syncthreads();
    }
    const float thr = s_red[0] + MARGIN;
    __syncthreads();

    #pragma unroll
    for (int i = 0; i < 4; i++) {
        if (dt[i] <= thr) {
            int idx = atomicAdd(&s_ncand, 1);
            if (idx < 64) s_cand[idx] = ci[i];
        }
    }
    __syncthreads();
    const int nc = s_ncand;

    if (nc <= 64) {
        for (int cc = wid; cc < nc; cc += 8) {
            int c = s_cand[cc];
            const float* cbr = cb + (size_t)c * DEMB;
            float dot = 0.0f;
            #pragma unroll
            for (int j = 0; j < 8; j++) dot = fmaf(s_z[lane + 32 * j], cbr[lane + 32 * j], dot);
            #pragma unroll
            for (int o = 16; o > 0; o >>= 1) dot += __shfl_xor_sync(0xffffffffu, dot, o);
            if (lane == 0) {
                float d = fmaf(-2.0f, dot, g_sqr[c]);
                unsigned u = __float_as_uint(d);
                u = (u & 0x80000000u) ? ~u : (u | 0x80000000u);
                atomicMin(&s_best, ((unsigned long long)u << 32) | (unsigned)c);
            }
        }
    } else {
        for (int c = wid; c < KCB; c += 8) {
            const float* cbr = cb + (size_t)c * DEMB;
            float dot = 0.0f;
            #pragma unroll
            for (int j = 0; j < 8; j++) dot = fmaf(s_z[lane + 32 * j], cbr[lane + 32 * j], dot);
            #pragma unroll
            for (int o = 16; o > 0; o >>= 1) dot += __shfl_xor_sync(0xffffffffu, dot, o);
            if (lane == 0) {
                float d = fmaf(-2.0f, dot, g_sqr[c]);
                unsigned u = __float_as_uint(d);
                u = (u & 0x80000000u) ? ~u : (u | 0x80000000u);
                atomicMin(&s_best, ((unsigned long long)u << 32) | (unsigned)c);
            }
        }
    }
    __syncthreads();

    // winner
    unsigned long long p = s_best;
    int code = (int)(unsigned)(p & 0xFFFFFFFFull);
    unsigned ue = (unsigned)(p >> 32);
    float dmin = (ue & 0x80000000u) ? __uint_as_float(ue & 0x7FFFFFFFu)
                                    : __uint_as_float(~ue);

    // fused scatter: segment-sum z, counts, loss
    atomicAdd(&g_upd[(size_t)code * DEMB + t], zval);
    float sq = zval * zval;
    #pragma unroll
    for (int o = 16; o > 0; o >>= 1) sq += __shfl_xor_sync(0xffffffffu, sq, o);
    if (lane == 0) s_red[wid] = sq;
    __syncthreads();
    if (t == 0) {
        float tot = 0.0f;
        #pragma unroll
        for (int w = 0; w < 8; w++) tot += s_red[w];
        g_codes[row] = code;
        g_dmin[row]  = dmin;
        out[OFF_CODES + row] = (float)code;
        atomicAdd(&g_loss, tot + dmin);
        atomicAdd(&g_cnt[code], 1.0f);
    }
}

// ===========================================================================
// transpose + tf32 hi/lo split
__global__ void k_trsplit(const float* __restrict__ src, float* __restrict__ hi,
                          float* __restrict__ lo, int R, int C) {
    int id = blockIdx.x * blockDim.x + threadIdx.x;
    int c = id / R, r = id - c * R;
    float v = src[(size_t)r * C + c];
    uint32_t h = f2tf32(v);
    float hf = __uint_as_float(h);
    hi[id] = hf;
    lo[id] = __uint_as_float(f2tf32(v - hf));
}

// codebook -> bf16 (hi only)
__global__ void k_convcb(const float* __restrict__ src, __nv_bfloat16* __restrict__ hi) {
    size_t i = ((size_t)blockIdx.x * blockDim.x + threadIdx.x) * 4;
    float4 v = *reinterpret_cast<const float4*>(src + i);
    __nv_bfloat162 h01 = __floats2bfloat162_rn(v.x, v.y);
    __nv_bfloat162 h23 = __floats2bfloat162_rn(v.z, v.w);
    uint2 hp;
    hp.x = *reinterpret_cast<uint32_t*>(&h01); hp.y = *reinterpret_cast<uint32_t*>(&h23);
    *reinterpret_cast<uint2*>(hi + i) = hp;
}

// ---------------------------------------------------------------------------
__global__ void k_init() {
    int i = blockIdx.x * blockDim.x + threadIdx.x;
    if (i < KCB * DEMB) g_upd[i] = 0.0f;
    if (i < KCB)        g_cnt[i] = 0.0f;
    if (i == 0)         g_loss  = 0.0f;
}

__global__ void k_sqr(const float* __restrict__ cb) {
    int k = blockIdx.x, j = threadIdx.x;
    float v = cb[k * DEMB + j];
    float s = v * v;
    #pragma unroll
    for (int o = 16; o > 0; o >>= 1) s += __shfl_xor_sync(0xffffffffu, s, o);
    __shared__ float wsum[8];
    if ((j & 31) == 0) wsum[j >> 5] = s;
    __syncthreads();
    if (j == 0) {
        float tot = 0.0f;
        #pragma unroll
        for (int w = 0; w < 8; w++) tot += wsum[w];
        g_sqr[k] = tot;
    }
}

__global__ __launch_bounds__(1024) void k_final_small(
    const float* __restrict__ ema_size_in, float* __restrict__ out)
{
    __shared__ float sh[1024];
    int t = threadIdx.x;
    float cnt = g_cnt[t];
    float esz = ema_size_in[t] + ALPHA * (cnt - ema_size_in[t]);
    out[OFF_EMA_SIZE + t] = esz;

    sh[t] = esz;
    __syncthreads();
    for (int s = 512; s > 0; s >>= 1) {
        if (t < s) sh[t] += sh[t + s];
        __syncthreads();
    }
    float n = sh[0];
    __syncthreads();

    float coef = n / (n + (float)KCB * EPSV);
    g_size[t]  = coef * (esz + EPSV);

    float p = cnt * (1.0f / (float)NROWS);
    float e = (cnt > 0.0f) ? (-p * logf(p)) : 0.0f;
    sh[t] = e;
    __syncthreads();
    for (int s = 512; s > 0; s >>= 1) {
        if (t < s) sh[t] += sh[t + s];
        __syncthreads();
    }
    if (t == 0) {
        out[OFF_ENT]    = sh[0] / logf(2.0f);
        out[OFF_EMB]    = g_loss;
        out[OFF_COMMIT] = g_loss;
    }
}

__global__ void k_ema(const float* __restrict__ ema_vecs_in, float* __restrict__ out) {
    int i = blockIdx.x * blockDim.x + threadIdx.x;
    float v = ema_vecs_in[i] + ALPHA * (g_upd[i] - ema_vecs_in[i]);
    out[OFF_EMA_VECS + i] = v;
    out[OFF_WEIGHT + i]   = v / g_size[i >> 8];
}

__global__ __launch_bounds__(256) void k_gather(float* __restrict__ out) {
    int row  = blockIdx.x;
    int code = g_codes[row];
    const float4* src = reinterpret_cast<const float4*>(g_Y + (size_t)code * DIN);
    float4* dst = reinterpret_cast<float4*>(out + OFF_X + (size_t)row * DIN);
    dst[threadIdx.x] = src[threadIdx.x];
}

// ---------------------------------------------------------------------------
extern "C" void kernel_launch(void* const* d_in, const int* in_sizes, int n_in,
                              void* d_out, int out_size) {
    const float* input    = (const float*)d_in[0];
    const float* W_send   = (const float*)d_in[1];
    const float* b_send   = (const float*)d_in[2];
    const float* W_recv   = (const float*)d_in[3];
    const float* b_recv   = (const float*)d_in[4];
    const float* codebook = (const float*)d_in[5];
    const float* ema_vecs = (const float*)d_in[6];
    const float* ema_size = (const float*)d_in[7];
    float* out = (float*)d_out;

    float *z_ptr, *Y_ptr, *wsh, *wsl, *wrh, *wrl;
    __nv_bfloat16 *zh, *cbh;
    cudaGetSymbolAddress((void**)&z_ptr, g_z);
    cudaGetSymbolAddress((void**)&Y_ptr, g_Y);
    cudaGetSymbolAddress((void**)&wsh, g_wsT_hi); cudaGetSymbolAddress((void**)&wsl, g_wsT_lo);
    cudaGetSymbolAddress((void**)&wrh, g_wrT_hi); cudaGetSymbolAddress((void**)&wrl, g_wrT_lo);
    cudaGetSymbolAddress((void**)&zh, g_zh);
    cudaGetSymbolAddress((void**)&cbh, g_cbh);

    cudaFuncSetAttribute(k_tgemm32, cudaFuncAttributeMaxDynamicSharedMemorySize, ZSMEM_BYTES);

    k_init<<<1024, 256>>>();                                              // 0
    k_trsplit<<<DIN * DEMB / 256, 256>>>(W_send, wsh, wsl, DIN, DEMB);    // 1
    k_trsplit<<<DIN * DEMB / 256, 256>>>(W_recv, wrh, wrl, DEMB, DIN);    // 2
    // z = input @ W_send + b_send (3xTF32, fused bf16-hi z output)       // 3 (profiled slot)
    // grid: (N/64, M/128) = (4, 128) = 512 CTAs
    k_tgemm32<<<dim3(4, 128), 256, ZSMEM_BYTES>>>(input, wsh, wsl, b_send,
                                                  z_ptr, zh, DEMB, DIN, 1);
    k_sqr<<<KCB, 256>>>(codebook);                                        // 4
    k_convcb<<<KCB * DEMB / 1024, 256>>>(codebook, cbh);                  // 5
    // Y = codebook @ W_recv + b_recv (3xTF32): grid (1024/64, 1024/128)  // 6
    k_tgemm32<<<dim3(16, 8), 256, ZSMEM_BYTES>>>(codebook, wrh, wrl, b_recv,
                                                 Y_ptr, (__nv_bfloat16*)nullptr,
                                                 DIN, DEMB, 0);
    k_cov<<<dim3(8, 128), 256>>>();                                       // 7
    k_refine<<<NROWS, 256>>>(codebook, out);                              // 8 (fused scatter)
    k_final_small<<<1, 1024>>>(ema_size, out);                            // 9
    k_ema<<<1024, 256>>>(ema_vecs, out);                                  // 10
    k_gather<<<NROWS, 256>>>(out);                                        // 11
}

// round 11
// speedup vs baseline: 1.4722x; 1.4721x over previous
#include <cuda_runtime.h>
#include <cuda_bf16.h>
#include <cuda_fp16.h>
#include <math.h>
#include <stdint.h>

// Problem constants
#define NROWS 16384
#define DIN   1024
#define DEMB  256
#define KCB   1024
#define ALPHA 0.01f
#define EPSV  1e-5f
#define MARGIN 4.0f

// Output layout (float32, tuple order concatenated)
#define OFF_X        ((size_t)0)
#define OFF_CODES    ((size_t)16777216)
#define OFF_EMB      ((size_t)16793600)
#define OFF_COMMIT   ((size_t)16793601)
#define OFF_ENT      ((size_t)16793602)
#define OFF_EMA_VECS ((size_t)16793603)
#define OFF_EMA_SIZE ((size_t)17055747)
#define OFF_WEIGHT   ((size_t)17056771)

// ---------------------------------------------------------------------------
// Scratch (device globals; no allocations allowed)
__device__ float g_z[NROWS * DEMB];
__device__ float g_sqr[KCB];
__device__ int   g_codes[NROWS];
__device__ float g_dmin[NROWS];
__device__ float g_upd[KCB * DEMB];
__device__ float g_cnt[KCB];
__device__ float g_loss;
__device__ float g_size[KCB];
__device__ float g_Y[KCB * DIN];
__device__ __half g_dist[NROWS * KCB];        // 32 MB approx distances (fp16)
__device__ __nv_bfloat16 g_zh[NROWS * DEMB];  // bf16 z for cov
__device__ __nv_bfloat16 g_cbh[KCB * DEMB];   // bf16 codebook for cov
// fp16 hi/lo operand splits (fp16x3 GEMMs)
__device__ __half g_inh[NROWS * DIN], g_inl[NROWS * DIN];     // input
__device__ __half g_wsh[DEMB * DIN],  g_wsl[DEMB * DIN];      // W_send^T [256,1024]
__device__ __half g_wrh[DIN * DEMB],  g_wrl[DIN * DEMB];      // W_recv^T [1024,256]
__device__ __half g_cbh16[KCB * DEMB], g_cbl16[KCB * DEMB];   // codebook

// ---------------------------------------------------------------------------
__device__ __forceinline__ uint32_t smem_u32(const void* p) {
    uint32_t a;
    asm("{ .reg .u64 t; cvta.to.shared.u64 t, %1; cvt.u32.u64 %0, t; }" : "=r"(a) : "l"(p));
    return a;
}
__device__ __forceinline__ void ldsm4(uint32_t* r, uint32_t addr) {
    asm volatile("ldmatrix.sync.aligned.m8n8.x4.shared.b16 {%0,%1,%2,%3}, [%4];"
                 : "=r"(r[0]), "=r"(r[1]), "=r"(r[2]), "=r"(r[3]) : "r"(addr));
}
__device__ __forceinline__ void mma_f16(float* c, const uint32_t* a, const uint32_t* b) {
    asm volatile("mma.sync.aligned.m16n8k16.row.col.f32.f16.f16.f32 "
                 "{%0,%1,%2,%3}, {%4,%5,%6,%7}, {%8,%9}, {%0,%1,%2,%3};"
                 : "+f"(c[0]), "+f"(c[1]), "+f"(c[2]), "+f"(c[3])
                 : "r"(a[0]), "r"(a[1]), "r"(a[2]), "r"(a[3]), "r"(b[0]), "r"(b[1]));
}
__device__ __forceinline__ void mma_bf16(float* c, const uint32_t* a, const uint32_t* b) {
    asm volatile("mma.sync.aligned.m16n8k16.row.col.f32.bf16.bf16.f32 "
                 "{%0,%1,%2,%3}, {%4,%5,%6,%7}, {%8,%9}, {%0,%1,%2,%3};"
                 : "+f"(c[0]), "+f"(c[1]), "+f"(c[2]), "+f"(c[3])
                 : "r"(a[0]), "r"(a[1]), "r"(a[2]), "r"(a[3]), "r"(b[0]), "r"(b[1]));
}
#define CP16(sm, gp) asm volatile("cp.async.ca.shared.global [%0], [%1], 16;" :: "r"(sm), "l"(gp))
#define CPCOMMIT()   asm volatile("cp.async.commit_group;" ::: "memory")
#define CPWAIT0()    asm volatile("cp.async.wait_group 0;" ::: "memory")
#define CPWAIT1()    asm volatile("cp.async.wait_group 1;" ::: "memory")

// ===========================================================================
// fp16x3 GEMM: C = (Ah+Al) @ (Bh+Bl)^T + bias, products hh + hl + lh.
// fp16 hi/lo chunks have 11-bit mantissas -> accuracy == 3xTF32, but
// m16n8k16 does 2x the K per mma.sync instruction (the measured bottleneck
// is per-SM mma.sync instruction rate ~0.23/cyc, shape-independent).
// CTA 128x128, BK=32, cp.async 2-stage. 8 warps 4(m)x2(n), warp 32x64.
// Addressing cloned from the validated cov kernel (quad-style B,
// consecutive-pair B regs; fcol-style A).
#define HSTRIDE 40
#define HARR (128 * HSTRIDE)          // fp16 units per tile array
#define HSTAGE (4 * HARR)             // Ah, Al, Bh, Bl
#define HSMEM_BYTES (2 * HSTAGE * 2)  // 81920

__device__ __forceinline__ void h_loads(uint32_t sbase, int buf,
    const __half* __restrict__ Ah, const __half* __restrict__ Al,
    const __half* __restrict__ Bh, const __half* __restrict__ Bl,
    int row0, int col0, int kdim, int kc, int tid)
{
    #pragma unroll
    for (int i = 0; i < 2; i++) {
        int seg = tid + i * 256;                 // 0..511
        int rr = seg >> 2, cc = (seg & 3) * 8;   // 128 rows x 32 cols fp16
        uint32_t so = sbase + (uint32_t)(buf * HSTAGE + rr * HSTRIDE + cc) * 2u;
        CP16(so,                  Ah + (size_t)(row0 + rr) * kdim + kc + cc);
        CP16(so + HARR * 2u,      Al + (size_t)(row0 + rr) * kdim + kc + cc);
        CP16(so + 2u * HARR * 2u, Bh + (size_t)(col0 + rr) * kdim + kc + cc);
        CP16(so + 3u * HARR * 2u, Bl + (size_t)(col0 + rr) * kdim + kc + cc);
    }
    CPCOMMIT();
}

__global__ __launch_bounds__(256, 2) void k_hgemm(
    const __half* __restrict__ Ah, const __half* __restrict__ Al,
    const __half* __restrict__ Bh, const __half* __restrict__ Bl,
    const float* __restrict__ bias, float* __restrict__ C,
    __nv_bfloat16* __restrict__ Chi, int ldc, int kdim, int write_bf)
{
    extern __shared__ __half hsm[];
    const int tid = threadIdx.x, lane = tid & 31, wid = tid >> 5;
    const int warp_m = wid & 3, warp_n = wid >> 2;   // 4 x 2
    const int row0 = blockIdx.y * 128, col0 = blockIdx.x * 128;
    const uint32_t sbase = smem_u32(hsm);
    const int quad = lane >> 3;

    float acc[2][8][4];
    #pragma unroll
    for (int a = 0; a < 2; a++)
        #pragma unroll
        for (int b = 0; b < 8; b++)
            #pragma unroll
            for (int c = 0; c < 4; c++) acc[a][b][c] = 0.0f;

    const int nch = kdim >> 5;
    h_loads(sbase, 0, Ah, Al, Bh, Bl, row0, col0, kdim, 0, tid);

    for (int c = 0; c < nch; c++) {
        if (c + 1 < nch) {
            h_loads(sbase, (c + 1) & 1, Ah, Al, Bh, Bl, row0, col0, kdim, (c + 1) * 32, tid);
            CPWAIT1();
        } else {
            CPWAIT0();
        }
        __syncthreads();
        const uint32_t sb = sbase + (uint32_t)((c & 1) * HSTAGE) * 2u;
        #pragma unroll
        for (int ks = 0; ks < 2; ks++) {
            const int k0 = ks * 16;
            uint32_t ahi[2][4], alo[2][4];
            #pragma unroll
            for (int mt = 0; mt < 2; mt++) {
                uint32_t aaddr = sb + (uint32_t)(((warp_m * 32 + mt * 16 + (lane & 15)) * HSTRIDE)
                                                 + k0 + (lane >> 4) * 8) * 2u;
                ldsm4(ahi[mt], aaddr);
                ldsm4(alo[mt], aaddr + HARR * 2u);
            }
            // B per-np: quad-style addressing -> n-group g uses CONSECUTIVE
            // regs {2g, 2g+1}  (cov-kernel validated R8-R10)
            #pragma unroll
            for (int np = 0; np < 4; np++) {
                uint32_t bh[4], bl[4];
                uint32_t baddr = sb + 2u * HARR * 2u +
                    (uint32_t)(((warp_n * 64 + np * 16 + (quad >> 1) * 8 + (lane & 7)) * HSTRIDE)
                               + k0 + (quad & 1) * 8) * 2u;
                ldsm4(bh, baddr);
                ldsm4(bl, baddr + HARR * 2u);
                #pragma unroll
                for (int mt = 0; mt < 2; mt++)
                    #pragma unroll
                    for (int g = 0; g < 2; g++) {
                        const int nt = np * 2 + g;
                        uint32_t vh[2] = {bh[g * 2], bh[g * 2 + 1]};
                        uint32_t vl[2] = {bl[g * 2], bl[g * 2 + 1]};
                        mma_f16(acc[mt][nt], ahi[mt], vh);
                        mma_f16(acc[mt][nt], ahi[mt], vl);
                        mma_f16(acc[mt][nt], alo[mt], vh);
                    }
            }
        }
        __syncthreads();
    }

    const int tr = lane >> 2, tc = (lane & 3) * 2;
    #pragma unroll
    for (int mt = 0; mt < 2; mt++)
        #pragma unroll
        for (int h = 0; h < 2; h++) {
            int row = row0 + warp_m * 32 + mt * 16 + h * 8 + tr;
            #pragma unroll
            for (int nt = 0; nt < 8; nt++) {
                int col = col0 + warp_n * 64 + nt * 8 + tc;
                float v0 = acc[mt][nt][h * 2 + 0] + bias[col];
                float v1 = acc[mt][nt][h * 2 + 1] + bias[col + 1];
                size_t o = (size_t)row * ldc + col;
                *reinterpret_cast<float2*>(C + o) = make_float2(v0, v1);
                if (write_bf) {
                    __nv_bfloat162 hp = __floats2bfloat162_rn(v0, v1);
                    *reinterpret_cast<uint32_t*>(Chi + o) = *reinterpret_cast<uint32_t*>(&hp);
                }
            }
        }
}

// ===========================================================================
// dist = sqr - 2 * (zh @ cbh^T), single bf16 product, fp16 output (32 MB).
// CTA 128x128, BK=32, cp.async 2-stage. 8 warps 4x2, warp 32x64, m16n8k16.
#define CSTRIDE 40
#define CARR (128 * CSTRIDE)   // bf16 units

__device__ __forceinline__ void cov_loads(uint32_t sbase, int buf,
                                          int row0, int code0, int kc, int tid)
{
    #pragma unroll
    for (int t = 0; t < 2; t++) {
        int seg = tid + t * 256;
        int rr = seg >> 2, cc = (seg & 3) * 8;
        uint32_t so = sbase + (uint32_t)(buf * 2 * CARR + rr * CSTRIDE + cc) * 2u;
        CP16(so,             g_zh  + (size_t)(row0 + rr) * DEMB + kc + cc);
        CP16(so + CARR * 2u, g_cbh + (size_t)(code0 + rr) * DEMB + kc + cc);
    }
    CPCOMMIT();
}

__global__ __launch_bounds__(256, 2) void k_cov()
{
    __shared__ __align__(16) __nv_bfloat16 sm[2][2][CARR];   // 40 KB
    __shared__ float s_sqr[128];
    const int tid = threadIdx.x, lane = tid & 31, wid = tid >> 5;
    const int warp_m = wid & 3, warp_n = wid >> 2;
    const int row0 = blockIdx.y * 128, code0 = blockIdx.x * 128;
    const uint32_t sbase = smem_u32(&sm[0][0][0]);
    const int quad = lane >> 3;

    if (tid < 128) s_sqr[tid] = g_sqr[code0 + tid];

    float acc[2][8][4];
    #pragma unroll
    for (int a = 0; a < 2; a++)
        #pragma unroll
        for (int b = 0; b < 8; b++)
            #pragma unroll
            for (int c = 0; c < 4; c++) acc[a][b][c] = 0.0f;

    cov_loads(sbase, 0, row0, code0, 0, tid);
    const int nch = DEMB >> 5;   // 8
    for (int c = 0; c < nch; c++) {
        if (c + 1 < nch) { cov_loads(sbase, (c + 1) & 1, row0, code0, (c + 1) * 32, tid); CPWAIT1(); }
        else CPWAIT0();
        __syncthreads();
        const uint32_t sb = sbase + (uint32_t)((c & 1) * 2 * CARR) * 2u;
        #pragma unroll
        for (int ks = 0; ks < 2; ks++) {
            const int k0 = ks * 16;
            uint32_t a[2][4];
            #pragma unroll
            for (int mt = 0; mt < 2; mt++)
                ldsm4(a[mt], sb + (uint32_t)(((warp_m * 32 + mt * 16 + (lane & 15)) * CSTRIDE)
                                             + k0 + (lane >> 4) * 8) * 2u);
            #pragma unroll
            for (int np = 0; np < 4; np++) {
                uint32_t b[4];
                ldsm4(b, sb + CARR * 2u +
                      (uint32_t)(((warp_n * 64 + np * 16 + (quad >> 1) * 8 + (lane & 7)) * CSTRIDE)
                                 + k0 + (quad & 1) * 8) * 2u);
                #pragma unroll
                for (int mt = 0; mt < 2; mt++)
                    #pragma unroll
                    for (int g = 0; g < 2; g++) {
                        uint32_t vb[2] = {b[g * 2], b[g * 2 + 1]};
                        mma_bf16(acc[mt][np * 2 + g], a[mt], vb);
                    }
            }
        }
        __syncthreads();
    }

    const int tr = lane >> 2, tc = (lane & 3) * 2;
    #pragma unroll
    for (int mt = 0; mt < 2; mt++)
        #pragma unroll
        for (int h = 0; h < 2; h++) {
            int row = row0 + warp_m * 32 + mt * 16 + h * 8 + tr;
            #pragma unroll
            for (int nt = 0; nt < 8; nt++) {
                int colL = warp_n * 64 + nt * 8 + tc;
                float d0 = fmaf(-2.0f, acc[mt][nt][h * 2 + 0], s_sqr[colL]);
                float d1 = fmaf(-2.0f, acc[mt][nt][h * 2 + 1], s_sqr[colL + 1]);
                __half2 hd;
                hd.x = __float2half_rn(d0);
                hd.y = __float2half_rn(d1);
                *reinterpret_cast<__half2*>(g_dist + (size_t)row * KCB + code0 + colL) = hd;
            }
        }
}

// ===========================================================================
// Refine + fused scatter: approx min from g_dist (fp16), exact fp32 distances
// for candidates, winner; then segment-sum z into g_upd, counts, loss.
__global__ __launch_bounds__(256) void k_refine(
    const float* __restrict__ cb, float* __restrict__ out)
{
    __shared__ float s_z[DEMB];
    __shared__ float s_red[256];
    __shared__ int   s_cand[64];
    __shared__ int   s_ncand;
    __shared__ unsigned long long s_best;

    const int row = blockIdx.x;
    const int t = threadIdx.x;
    const int wid = t >> 5, lane = t & 31;

    float zval = g_z[(size_t)row * DEMB + t];
    s_z[t] = zval;
    if (t == 0) { s_ncand = 0; s_best = 0xFFFFFFFFFFFFFFFFull; }

    const __half2* drow = reinterpret_cast<const __half2*>(g_dist + (size_t)row * KCB);
    __half2 p0 = drow[t];
    __half2 p1 = drow[256 + t];
    float dt[4];
    int   ci[4];
    dt[0] = __half2float(p0.x); ci[0] = 2 * t;
    dt[1] = __half2float(p0.y); ci[1] = 2 * t + 1;
    dt[2] = __half2float(p1.x); ci[2] = 512 + 2 * t;
    dt[3] = __half2float(p1.y); ci[3] = 512 + 2 * t + 1;
    float lm = fminf(fminf(dt[0], dt[1]), fminf(dt[2], dt[3]));

    s_red[t] = lm;
    __syncthreads();
    for (int s = 128; s > 0; s >>= 1) {
        if (t < s) s_red[t] = fminf(s_red[t], s_red[t + s]);
        __syncthreads();
    }
    const float thr = s_red[0] + MARGIN;
    __syncthreads();

    #pragma unroll
    for (int i = 0; i < 4; i++) {
        if (dt[i] <= thr) {
            int idx = atomicAdd(&s_ncand, 1);
            if (idx < 64) s_cand[idx] = ci[i];
        }
    }
    __syncthreads();
    const int nc = s_ncand;

    if (nc <= 64) {
        for (int cc = wid; cc < nc; cc += 8) {
            int c = s_cand[cc];
            const float* cbr = cb + (size_t)c * DEMB;
            float dot = 0.0f;
            #pragma unroll
            for (int j = 0; j < 8; j++) dot = fmaf(s_z[lane + 32 * j], cbr[lane + 32 * j], dot);
            #pragma unroll
            for (int o = 16; o > 0; o >>= 1) dot += __shfl_xor_sync(0xffffffffu, dot, o);
            if (lane == 0) {
                float d = fmaf(-2.0f, dot, g_sqr[c]);
                unsigned u = __float_as_uint(d);
                u = (u & 0x80000000u) ? ~u : (u | 0x80000000u);
                atomicMin(&s_best, ((unsigned long long)u << 32) | (unsigned)c);
            }
        }
    } else {
        for (int c = wid; c < KCB; c += 8) {
            const float* cbr = cb + (size_t)c * DEMB;
            float dot = 0.0f;
            #pragma unroll
            for (int j = 0; j < 8; j++) dot = fmaf(s_z[lane + 32 * j], cbr[lane + 32 * j], dot);
            #pragma unroll
            for (int o = 16; o > 0; o >>= 1) dot += __shfl_xor_sync(0xffffffffu, dot, o);
            if (lane == 0) {
                float d = fmaf(-2.0f, dot, g_sqr[c]);
                unsigned u = __float_as_uint(d);
                u = (u & 0x80000000u) ? ~u : (u | 0x80000000u);
                atomicMin(&s_best, ((unsigned long long)u << 32) | (unsigned)c);
            }
        }
    }
    __syncthreads();

    unsigned long long p = s_best;
    int code = (int)(unsigned)(p & 0xFFFFFFFFull);
    unsigned ue = (unsigned)(p >> 32);
    float dmin = (ue & 0x80000000u) ? __uint_as_float(ue & 0x7FFFFFFFu)
                                    : __uint_as_float(~ue);

    atomicAdd(&g_upd[(size_t)code * DEMB + t], zval);
    float sq = zval * zval;
    #pragma unroll
    for (int o = 16; o > 0; o >>= 1) sq += __shfl_xor_sync(0xffffffffu, sq, o);
    if (lane == 0) s_red[wid] = sq;
    __syncthreads();
    if (t == 0) {
        float tot = 0.0f;
        #pragma unroll
        for (int w = 0; w < 8; w++) tot += s_red[w];
        g_codes[row] = code;
        g_dmin[row]  = dmin;
        out[OFF_CODES + row] = (float)code;
        atomicAdd(&g_loss, tot + dmin);
        atomicAdd(&g_cnt[code], 1.0f);
    }
}

// ===========================================================================
// elementwise fp32 -> fp16 hi/lo split (float4 per thread)
__global__ void k_split16(const float* __restrict__ src, __half* __restrict__ hi,
                          __half* __restrict__ lo) {
    size_t i = ((size_t)blockIdx.x * blockDim.x + threadIdx.x) * 4;
    float4 v = *reinterpret_cast<const float4*>(src + i);
    __half hx = __float2half_rn(v.x), hy = __float2half_rn(v.y);
    __half hz = __float2half_rn(v.z), hw = __float2half_rn(v.w);
    __half lx = __float2half_rn(v.x - __half2float(hx));
    __half ly = __float2half_rn(v.y - __half2float(hy));
    __half lz = __float2half_rn(v.z - __half2float(hz));
    __half lw = __float2half_rn(v.w - __half2float(hw));
    __half2 h01 = __halves2half2(hx, hy), h23 = __halves2half2(hz, hw);
    __half2 l01 = __halves2half2(lx, ly), l23 = __halves2half2(lz, lw);
    uint2 hp, lp;
    hp.x = *reinterpret_cast<uint32_t*>(&h01); hp.y = *reinterpret_cast<uint32_t*>(&h23);
    lp.x = *reinterpret_cast<uint32_t*>(&l01); lp.y = *reinterpret_cast<uint32_t*>(&l23);
    *reinterpret_cast<uint2*>(hi + i) = hp;
    *reinterpret_cast<uint2*>(lo + i) = lp;
}

// transpose + fp16 hi/lo split: dst[C,R] = split(src[R,C]^T)
__global__ void k_trsplit16(const float* __restrict__ src, __half* __restrict__ hi,
                            __half* __restrict__ lo, int R, int C) {
    int id = blockIdx.x * blockDim.x + threadIdx.x;
    int c = id / R, r = id - c * R;
    float v = src[(size_t)r * C + c];
    __half h = __float2half_rn(v);
    hi[id] = h;
    lo[id] = __float2half_rn(v - __half2float(h));
}

// codebook -> bf16 (hi only, for cov)
__global__ void k_convcb(const float* __restrict__ src, __nv_bfloat16* __restrict__ hi) {
    size_t i = ((size_t)blockIdx.x * blockDim.x + threadIdx.x) * 4;
    float4 v = *reinterpret_cast<const float4*>(src + i);
    __nv_bfloat162 h01 = __floats2bfloat162_rn(v.x, v.y);
    __nv_bfloat162 h23 = __floats2bfloat162_rn(v.z, v.w);
    uint2 hp;
    hp.x = *reinterpret_cast<uint32_t*>(&h01); hp.y = *reinterpret_cast<uint32_t*>(&h23);
    *reinterpret_cast<uint2*>(hi + i) = hp;
}

// ---------------------------------------------------------------------------
__global__ void k_init() {
    int i = blockIdx.x * blockDim.x + threadIdx.x;
    if (i < KCB * DEMB) g_upd[i] = 0.0f;
    if (i < KCB)        g_cnt[i] = 0.0f;
    if (i == 0)         g_loss  = 0.0f;
}

__global__ void k_sqr(const float* __restrict__ cb) {
    int k = blockIdx.x, j = threadIdx.x;
    float v = cb[k * DEMB + j];
    float s = v * v;
    #pragma unroll
    for (int o = 16; o > 0; o >>= 1) s += __shfl_xor_sync(0xffffffffu, s, o);
    __shared__ float wsum[8];
    if ((j & 31) == 0) wsum[j >> 5] = s;
    __syncthreads();
    if (j == 0) {
        float tot = 0.0f;
        #pragma unroll
        for (int w = 0; w < 8; w++) tot += wsum[w];
        g_sqr[k] = tot;
    }
}

__global__ __launch_bounds__(1024) void k_final_small(
    const float* __restrict__ ema_size_in, float* __restrict__ out)
{
    __shared__ float sh[1024];
    int t = threadIdx.x;
    float cnt = g_cnt[t];
    float esz = ema_size_in[t] + ALPHA * (cnt - ema_size_in[t]);
    out[OFF_EMA_SIZE + t] = esz;

    sh[t] = esz;
    __syncthreads();
    for (int s = 512; s > 0; s >>= 1) {
        if (t < s) sh[t] += sh[t + s];
        __syncthreads();
    }
    float n = sh[0];
    __syncthreads();

    float coef = n / (n + (float)KCB * EPSV);
    g_size[t]  = coef * (esz + EPSV);

    float p = cnt * (1.0f / (float)NROWS);
    float e = (cnt > 0.0f) ? (-p * logf(p)) : 0.0f;
    sh[t] = e;
    __syncthreads();
    for (int s = 512; s > 0; s >>= 1) {
        if (t < s) sh[t] += sh[t + s];
        __syncthreads();
    }
    if (t == 0) {
        out[OFF_ENT]    = sh[0] / logf(2.0f);
        out[OFF_EMB]    = g_loss;
        out[OFF_COMMIT] = g_loss;
    }
}

__global__ void k_ema(const float* __restrict__ ema_vecs_in, float* __restrict__ out) {
    int i = blockIdx.x * blockDim.x + threadIdx.x;
    float v = ema_vecs_in[i] + ALPHA * (g_upd[i] - ema_vecs_in[i]);
    out[OFF_EMA_VECS + i] = v;
    out[OFF_WEIGHT + i]   = v / g_size[i >> 8];
}

__global__ __launch_bounds__(256) void k_gather(float* __restrict__ out) {
    int row  = blockIdx.x;
    int code = g_codes[row];
    const float4* src = reinterpret_cast<const float4*>(g_Y + (size_t)code * DIN);
    float4* dst = reinterpret_cast<float4*>(out + OFF_X + (size_t)row * DIN);
    dst[threadIdx.x] = src[threadIdx.x];
}

// ---------------------------------------------------------------------------
extern "C" void kernel_launch(void* const* d_in, const int* in_sizes, int n_in,
                              void* d_out, int out_size) {
    const float* input    = (const float*)d_in[0];
    const float* W_send   = (const float*)d_in[1];
    const float* b_send   = (const float*)d_in[2];
    const float* W_recv   = (const float*)d_in[3];
    const float* b_recv   = (const float*)d_in[4];
    const float* codebook = (const float*)d_in[5];
    const float* ema_vecs = (const float*)d_in[6];
    const float* ema_size = (const float*)d_in[7];
    float* out = (float*)d_out;

    float *z_ptr, *Y_ptr;
    __half *inh, *inl, *wsh, *wsl, *wrh, *wrl, *cb16h, *cb16l;
    __nv_bfloat16 *zh, *cbh;
    cudaGetSymbolAddress((void**)&z_ptr, g_z);
    cudaGetSymbolAddress((void**)&Y_ptr, g_Y);
    cudaGetSymbolAddress((void**)&inh, g_inh);   cudaGetSymbolAddress((void**)&inl, g_inl);
    cudaGetSymbolAddress((void**)&wsh, g_wsh);   cudaGetSymbolAddress((void**)&wsl, g_wsl);
    cudaGetSymbolAddress((void**)&wrh, g_wrh);   cudaGetSymbolAddress((void**)&wrl, g_wrl);
    cudaGetSymbolAddress((void**)&cb16h, g_cbh16); cudaGetSymbolAddress((void**)&cb16l, g_cbl16);
    cudaGetSymbolAddress((void**)&zh, g_zh);
    cudaGetSymbolAddress((void**)&cbh, g_cbh);

    cudaFuncSetAttribute(k_hgemm, cudaFuncAttributeMaxDynamicSharedMemorySize, HSMEM_BYTES);

    k_init<<<1024, 256>>>();                                              // 0
    k_split16<<<NROWS * DIN / 1024, 256>>>(input, inh, inl);              // 1
    k_trsplit16<<<DIN * DEMB / 256, 256>>>(W_send, wsh, wsl, DIN, DEMB);  // 2
    // z = input @ W_send + b_send (fp16x3, fused bf16 z out)             // 3 (profiled slot)
    k_hgemm<<<dim3(2, 128), 256, HSMEM_BYTES>>>(inh, inl, wsh, wsl, b_send,
                                                z_ptr, zh, DEMB, DIN, 1);
    k_trsplit16<<<DIN * DEMB / 256, 256>>>(W_recv, wrh, wrl, DEMB, DIN);  // 4
    k_split16<<<KCB * DEMB / 1024, 256>>>(codebook, cb16h, cb16l);        // 5
    k_sqr<<<KCB, 256>>>(codebook);                                        // 6
    k_convcb<<<KCB * DEMB / 1024, 256>>>(codebook, cbh);                  // 7
    // Y = codebook @ W_recv + b_recv (fp16x3)                            // 8
    k_hgemm<<<dim3(8, 8), 256, HSMEM_BYTES>>>(cb16h, cb16l, wrh, wrl, b_recv,
                                              Y_ptr, (__nv_bfloat16*)nullptr,
                                              DIN, DEMB, 0);
    k_cov<<<dim3(8, 128), 256>>>();                                       // 9
    k_refine<<<NROWS, 256>>>(codebook, out);                              // 10
    k_final_small<<<1, 1024>>>(ema_size, out);                            // 11
    k_ema<<<1024, 256>>>(ema_vecs, out);                                  // 12
    k_gather<<<NROWS, 256>>>(out);                                        // 13
}

// round 12
// speedup vs baseline: 1.7285x; 1.1741x over previous
#include <cuda_runtime.h>
#include <cuda_bf16.h>
#include <cuda_fp16.h>
#include <math.h>
#include <stdint.h>

// Problem constants
#define NROWS 16384
#define DIN   1024
#define DEMB  256
#define KCB   1024
#define ALPHA 0.01f
#define EPSV  1e-5f
#define MARGIN 4.0f

// Output layout (float32, tuple order concatenated)
#define OFF_X        ((size_t)0)
#define OFF_CODES    ((size_t)16777216)
#define OFF_EMB      ((size_t)16793600)
#define OFF_COMMIT   ((size_t)16793601)
#define OFF_ENT      ((size_t)16793602)
#define OFF_EMA_VECS ((size_t)16793603)
#define OFF_EMA_SIZE ((size_t)17055747)
#define OFF_WEIGHT   ((size_t)17056771)

// ---------------------------------------------------------------------------
// Scratch (device globals; no allocations allowed)
__device__ float g_z[NROWS * DEMB];
__device__ float g_sqr[KCB];
__device__ int   g_codes[NROWS];
__device__ float g_dmin[NROWS];
__device__ float g_upd[KCB * DEMB];
__device__ float g_cnt[KCB];
__device__ float g_loss;
__device__ float g_size[KCB];
__device__ float g_Y[KCB * DIN];
__device__ __half g_dist[NROWS * KCB];        // 32 MB approx distances (fp16)
__device__ __nv_bfloat16 g_zh[NROWS * DEMB];  // bf16 z for cov
__device__ __nv_bfloat16 g_cbh[KCB * DEMB];   // bf16 codebook for cov
// fp16 hi/lo operand splits
__device__ __half g_wsh[DEMB * DIN],  g_wsl[DEMB * DIN];      // W_send^T [256,1024]
__device__ __half g_wrh[DIN * DEMB],  g_wrl[DIN * DEMB];      // W_recv^T [1024,256]
__device__ __half g_cbh16[KCB * DEMB], g_cbl16[KCB * DEMB];   // codebook

// ---------------------------------------------------------------------------
__device__ __forceinline__ uint32_t smem_u32(const void* p) {
    uint32_t a;
    asm("{ .reg .u64 t; cvta.to.shared.u64 t, %1; cvt.u32.u64 %0, t; }" : "=r"(a) : "l"(p));
    return a;
}
__device__ __forceinline__ void ldsm4(uint32_t* r, uint32_t addr) {
    asm volatile("ldmatrix.sync.aligned.m8n8.x4.shared.b16 {%0,%1,%2,%3}, [%4];"
                 : "=r"(r[0]), "=r"(r[1]), "=r"(r[2]), "=r"(r[3]) : "r"(addr));
}
__device__ __forceinline__ void mma_f16(float* c, const uint32_t* a, const uint32_t* b) {
    asm volatile("mma.sync.aligned.m16n8k16.row.col.f32.f16.f16.f32 "
                 "{%0,%1,%2,%3}, {%4,%5,%6,%7}, {%8,%9}, {%0,%1,%2,%3};"
                 : "+f"(c[0]), "+f"(c[1]), "+f"(c[2]), "+f"(c[3])
                 : "r"(a[0]), "r"(a[1]), "r"(a[2]), "r"(a[3]), "r"(b[0]), "r"(b[1]));
}
__device__ __forceinline__ void mma_bf16(float* c, const uint32_t* a, const uint32_t* b) {
    asm volatile("mma.sync.aligned.m16n8k16.row.col.f32.bf16.bf16.f32 "
                 "{%0,%1,%2,%3}, {%4,%5,%6,%7}, {%8,%9}, {%0,%1,%2,%3};"
                 : "+f"(c[0]), "+f"(c[1]), "+f"(c[2]), "+f"(c[3])
                 : "r"(a[0]), "r"(a[1]), "r"(a[2]), "r"(a[3]), "r"(b[0]), "r"(b[1]));
}
#define CP16(sm, gp) asm volatile("cp.async.ca.shared.global [%0], [%1], 16;" :: "r"(sm), "l"(gp))
#define CPCOMMIT()   asm volatile("cp.async.commit_group;" ::: "memory")
#define CPWAIT0()    asm volatile("cp.async.wait_group 0;" ::: "memory")
#define CPWAIT1()    asm volatile("cp.async.wait_group 1;" ::: "memory")

// smem tile geometry (shared by both fp16 GEMMs; ldsm addressing validated R8-R11)
#define HSTRIDE 40
#define HARR (128 * HSTRIDE)          // fp16 units per tile array
#define HSTAGE (4 * HARR)             // Ah, Al, Bh, Bl
#define HSMEM_BYTES (2 * HSTAGE * 2)  // 81920

// ===========================================================================
// z GEMM (fp16x3) with FUSED A split: A is fp32 in gmem; each thread LDGs
// 16 floats/chunk, converts to fp16 hi/lo in-register, STS into the same
// smem layout the validated ldsm/mma core reads. B (weights) pre-split fp16.
__device__ __forceinline__ void zb_loads(uint32_t sbase, int buf,
    const __half* __restrict__ Bh, const __half* __restrict__ Bl,
    int col0, int kdim, int kc, int tid)
{
    #pragma unroll
    for (int i = 0; i < 2; i++) {
        int seg = tid + i * 256;
        int rr = seg >> 2, cc = (seg & 3) * 8;
        uint32_t so = sbase + (uint32_t)(buf * HSTAGE + rr * HSTRIDE + cc) * 2u;
        CP16(so + 2u * HARR * 2u, Bh + (size_t)(col0 + rr) * kdim + kc + cc);
        CP16(so + 3u * HARR * 2u, Bl + (size_t)(col0 + rr) * kdim + kc + cc);
    }
    CPCOMMIT();
}

__global__ __launch_bounds__(256, 2) void k_zgemm(
    const float* __restrict__ A,
    const __half* __restrict__ Bh, const __half* __restrict__ Bl,
    const float* __restrict__ bias, float* __restrict__ C,
    __nv_bfloat16* __restrict__ Chi, int ldc, int kdim)
{
    extern __shared__ __half hsm[];
    const int tid = threadIdx.x, lane = tid & 31, wid = tid >> 5;
    const int warp_m = wid & 3, warp_n = wid >> 2;
    const int row0 = blockIdx.y * 128, col0 = blockIdx.x * 128;
    const uint32_t sbase = smem_u32(hsm);
    const int quad = lane >> 3;

    const int arr = tid >> 1;           // A row 0..127
    const int acb = (tid & 1) * 16;     // A col base 0/16

    float areg[16];
    float acc[2][8][4];
    #pragma unroll
    for (int a = 0; a < 2; a++)
        #pragma unroll
        for (int b = 0; b < 8; b++)
            #pragma unroll
            for (int c = 0; c < 4; c++) acc[a][b][c] = 0.0f;

    const int nch = kdim >> 5;

    // A load / convert / store helpers
    const float* Abase = A + (size_t)(row0 + arr) * kdim + acb;
    #define LDGA(kc) do { \
        const float* _p = Abase + (kc); \
        *reinterpret_cast<float4*>(areg + 0)  = *reinterpret_cast<const float4*>(_p); \
        *reinterpret_cast<float4*>(areg + 4)  = *reinterpret_cast<const float4*>(_p + 4); \
        *reinterpret_cast<float4*>(areg + 8)  = *reinterpret_cast<const float4*>(_p + 8); \
        *reinterpret_cast<float4*>(areg + 12) = *reinterpret_cast<const float4*>(_p + 12); \
    } while (0)
    #define STSA(buf) do { \
        __half hh[16], ll[16]; \
        _Pragma("unroll") \
        for (int q = 0; q < 16; q++) { \
            hh[q] = __float2half_rn(areg[q]); \
            ll[q] = __float2half_rn(areg[q] - __half2float(hh[q])); \
        } \
        uint32_t _o = (uint32_t)((buf) * HSTAGE + arr * HSTRIDE + acb); \
        __half* _ah = hsm + _o; \
        __half* _al = hsm + _o + HARR; \
        *reinterpret_cast<uint4*>(_ah)     = *reinterpret_cast<uint4*>(hh); \
        *reinterpret_cast<uint4*>(_ah + 8) = *reinterpret_cast<uint4*>(hh + 8); \
        *reinterpret_cast<uint4*>(_al)     = *reinterpret_cast<uint4*>(ll); \
        *reinterpret_cast<uint4*>(_al + 8) = *reinterpret_cast<uint4*>(ll + 8); \
    } while (0)

    LDGA(0);
    STSA(0);
    zb_loads(sbase, 0, Bh, Bl, col0, kdim, 0, tid);

    for (int c = 0; c < nch; c++) {
        if (c + 1 < nch) {
            LDGA((c + 1) * 32);
            zb_loads(sbase, (c + 1) & 1, Bh, Bl, col0, kdim, (c + 1) * 32, tid);
            CPWAIT1();
        } else {
            CPWAIT0();
        }
        __syncthreads();
        const uint32_t sb = sbase + (uint32_t)((c & 1) * HSTAGE) * 2u;
        #pragma unroll
        for (int ks = 0; ks < 2; ks++) {
            const int k0 = ks * 16;
            uint32_t ahi[2][4], alo[2][4];
            #pragma unroll
            for (int mt = 0; mt < 2; mt++) {
                uint32_t aaddr = sb + (uint32_t)(((warp_m * 32 + mt * 16 + (lane & 15)) * HSTRIDE)
                                                 + k0 + (lane >> 4) * 8) * 2u;
                ldsm4(ahi[mt], aaddr);
                ldsm4(alo[mt], aaddr + HARR * 2u);
            }
            #pragma unroll
            for (int np = 0; np < 4; np++) {
                uint32_t bh[4], bl[4];
                uint32_t baddr = sb + 2u * HARR * 2u +
                    (uint32_t)(((warp_n * 64 + np * 16 + (quad >> 1) * 8 + (lane & 7)) * HSTRIDE)
                               + k0 + (quad & 1) * 8) * 2u;
                ldsm4(bh, baddr);
                ldsm4(bl, baddr + HARR * 2u);
                #pragma unroll
                for (int mt = 0; mt < 2; mt++)
                    #pragma unroll
                    for (int g = 0; g < 2; g++) {
                        const int nt = np * 2 + g;
                        uint32_t vh[2] = {bh[g * 2], bh[g * 2 + 1]};
                        uint32_t vl[2] = {bl[g * 2], bl[g * 2 + 1]};
                        mma_f16(acc[mt][nt], ahi[mt], vh);
                        mma_f16(acc[mt][nt], ahi[mt], vl);
                        mma_f16(acc[mt][nt], alo[mt], vh);
                    }
            }
        }
        if (c + 1 < nch) STSA((c + 1) & 1);
        __syncthreads();
    }

    const int tr = lane >> 2, tc = (lane & 3) * 2;
    #pragma unroll
    for (int mt = 0; mt < 2; mt++)
        #pragma unroll
        for (int h = 0; h < 2; h++) {
            int row = row0 + warp_m * 32 + mt * 16 + h * 8 + tr;
            #pragma unroll
            for (int nt = 0; nt < 8; nt++) {
                int col = col0 + warp_n * 64 + nt * 8 + tc;
                float v0 = acc[mt][nt][h * 2 + 0] + bias[col];
                float v1 = acc[mt][nt][h * 2 + 1] + bias[col + 1];
                size_t o = (size_t)row * ldc + col;
                *reinterpret_cast<float2*>(C + o) = make_float2(v0, v1);
                __nv_bfloat162 hp = __floats2bfloat162_rn(v0, v1);
                *reinterpret_cast<uint32_t*>(Chi + o) = *reinterpret_cast<uint32_t*>(&hp);
            }
        }
}

// ===========================================================================
// fp16x3 GEMM with pre-split A and B (used for Y). Structure == R11.
__device__ __forceinline__ void h_loads(uint32_t sbase, int buf,
    const __half* __restrict__ Ah, const __half* __restrict__ Al,
    const __half* __restrict__ Bh, const __half* __restrict__ Bl,
    int row0, int col0, int kdim, int kc, int tid)
{
    #pragma unroll
    for (int i = 0; i < 2; i++) {
        int seg = tid + i * 256;
        int rr = seg >> 2, cc = (seg & 3) * 8;
        uint32_t so = sbase + (uint32_t)(buf * HSTAGE + rr * HSTRIDE + cc) * 2u;
        CP16(so,                  Ah + (size_t)(row0 + rr) * kdim + kc + cc);
        CP16(so + HARR * 2u,      Al + (size_t)(row0 + rr) * kdim + kc + cc);
        CP16(so + 2u * HARR * 2u, Bh + (size_t)(col0 + rr) * kdim + kc + cc);
        CP16(so + 3u * HARR * 2u, Bl + (size_t)(col0 + rr) * kdim + kc + cc);
    }
    CPCOMMIT();
}

__global__ __launch_bounds__(256, 2) void k_hgemm(
    const __half* __restrict__ Ah, const __half* __restrict__ Al,
    const __half* __restrict__ Bh, const __half* __restrict__ Bl,
    const float* __restrict__ bias, float* __restrict__ C,
    int ldc, int kdim)
{
    extern __shared__ __half hsm[];
    const int tid = threadIdx.x, lane = tid & 31, wid = tid >> 5;
    const int warp_m = wid & 3, warp_n = wid >> 2;
    const int row0 = blockIdx.y * 128, col0 = blockIdx.x * 128;
    const uint32_t sbase = smem_u32(hsm);
    const int quad = lane >> 3;

    float acc[2][8][4];
    #pragma unroll
    for (int a = 0; a < 2; a++)
        #pragma unroll
        for (int b = 0; b < 8; b++)
            #pragma unroll
            for (int c = 0; c < 4; c++) acc[a][b][c] = 0.0f;

    const int nch = kdim >> 5;
    h_loads(sbase, 0, Ah, Al, Bh, Bl, row0, col0, kdim, 0, tid);

    for (int c = 0; c < nch; c++) {
        if (c + 1 < nch) {
            h_loads(sbase, (c + 1) & 1, Ah, Al, Bh, Bl, row0, col0, kdim, (c + 1) * 32, tid);
            CPWAIT1();
        } else {
            CPWAIT0();
        }
        __syncthreads();
        const uint32_t sb = sbase + (uint32_t)((c & 1) * HSTAGE) * 2u;
        #pragma unroll
        for (int ks = 0; ks < 2; ks++) {
            const int k0 = ks * 16;
            uint32_t ahi[2][4], alo[2][4];
            #pragma unroll
            for (int mt = 0; mt < 2; mt++) {
                uint32_t aaddr = sb + (uint32_t)(((warp_m * 32 + mt * 16 + (lane & 15)) * HSTRIDE)
                                                 + k0 + (lane >> 4) * 8) * 2u;
                ldsm4(ahi[mt], aaddr);
                ldsm4(alo[mt], aaddr + HARR * 2u);
            }
            #pragma unroll
            for (int np = 0; np < 4; np++) {
                uint32_t bh[4], bl[4];
                uint32_t baddr = sb + 2u * HARR * 2u +
                    (uint32_t)(((warp_n * 64 + np * 16 + (quad >> 1) * 8 + (lane & 7)) * HSTRIDE)
                               + k0 + (quad & 1) * 8) * 2u;
                ldsm4(bh, baddr);
                ldsm4(bl, baddr + HARR * 2u);
                #pragma unroll
                for (int mt = 0; mt < 2; mt++)
                    #pragma unroll
                    for (int g = 0; g < 2; g++) {
                        const int nt = np * 2 + g;
                        uint32_t vh[2] = {bh[g * 2], bh[g * 2 + 1]};
                        uint32_t vl[2] = {bl[g * 2], bl[g * 2 + 1]};
                        mma_f16(acc[mt][nt], ahi[mt], vh);
                        mma_f16(acc[mt][nt], ahi[mt], vl);
                        mma_f16(acc[mt][nt], alo[mt], vh);
                    }
            }
        }
        __syncthreads();
    }

    const int tr = lane >> 2, tc = (lane & 3) * 2;
    #pragma unroll
    for (int mt = 0; mt < 2; mt++)
        #pragma unroll
        for (int h = 0; h < 2; h++) {
            int row = row0 + warp_m * 32 + mt * 16 + h * 8 + tr;
            #pragma unroll
            for (int nt = 0; nt < 8; nt++) {
                int col = col0 + warp_n * 64 + nt * 8 + tc;
                float v0 = acc[mt][nt][h * 2 + 0] + bias[col];
                float v1 = acc[mt][nt][h * 2 + 1] + bias[col + 1];
                *reinterpret_cast<float2*>(C + (size_t)row * ldc + col) = make_float2(v0, v1);
            }
        }
}

// ===========================================================================
// dist = sqr - 2 * (zh @ cbh^T), single bf16 product, fp16 output (32 MB).
#define CSTRIDE 40
#define CARR (128 * CSTRIDE)

__device__ __forceinline__ void cov_loads(uint32_t sbase, int buf,
                                          int row0, int code0, int kc, int tid)
{
    #pragma unroll
    for (int t = 0; t < 2; t++) {
        int seg = tid + t * 256;
        int rr = seg >> 2, cc = (seg & 3) * 8;
        uint32_t so = sbase + (uint32_t)(buf * 2 * CARR + rr * CSTRIDE + cc) * 2u;
        CP16(so,             g_zh  + (size_t)(row0 + rr) * DEMB + kc + cc);
        CP16(so + CARR * 2u, g_cbh + (size_t)(code0 + rr) * DEMB + kc + cc);
    }
    CPCOMMIT();
}

__global__ __launch_bounds__(256, 2) void k_cov()
{
    __shared__ __align__(16) __nv_bfloat16 sm[2][2][CARR];
    __shared__ float s_sqr[128];
    const int tid = threadIdx.x, lane = tid & 31, wid = tid >> 5;
    const int warp_m = wid & 3, warp_n = wid >> 2;
    const int row0 = blockIdx.y * 128, code0 = blockIdx.x * 128;
    const uint32_t sbase = smem_u32(&sm[0][0][0]);
    const int quad = lane >> 3;

    if (tid < 128) s_sqr[tid] = g_sqr[code0 + tid];

    float acc[2][8][4];
    #pragma unroll
    for (int a = 0; a < 2; a++)
        #pragma unroll
        for (int b = 0; b < 8; b++)
            #pragma unroll
            for (int c = 0; c < 4; c++) acc[a][b][c] = 0.0f;

    cov_loads(sbase, 0, row0, code0, 0, tid);
    const int nch = DEMB >> 5;
    for (int c = 0; c < nch; c++) {
        if (c + 1 < nch) { cov_loads(sbase, (c + 1) & 1, row0, code0, (c + 1) * 32, tid); CPWAIT1(); }
        else CPWAIT0();
        __syncthreads();
        const uint32_t sb = sbase + (uint32_t)((c & 1) * 2 * CARR) * 2u;
        #pragma unroll
        for (int ks = 0; ks < 2; ks++) {
            const int k0 = ks * 16;
            uint32_t a[2][4];
            #pragma unroll
            for (int mt = 0; mt < 2; mt++)
                ldsm4(a[mt], sb + (uint32_t)(((warp_m * 32 + mt * 16 + (lane & 15)) * CSTRIDE)
                                             + k0 + (lane >> 4) * 8) * 2u);
            #pragma unroll
            for (int np = 0; np < 4; np++) {
                uint32_t b[4];
                ldsm4(b, sb + CARR * 2u +
                      (uint32_t)(((warp_n * 64 + np * 16 + (quad >> 1) * 8 + (lane & 7)) * CSTRIDE)
                                 + k0 + (quad & 1) * 8) * 2u);
                #pragma unroll
                for (int mt = 0; mt < 2; mt++)
                    #pragma unroll
                    for (int g = 0; g < 2; g++) {
                        uint32_t vb[2] = {b[g * 2], b[g * 2 + 1]};
                        mma_bf16(acc[mt][np * 2 + g], a[mt], vb);
                    }
            }
        }
        __syncthreads();
    }

    const int tr = lane >> 2, tc = (lane & 3) * 2;
    #pragma unroll
    for (int mt = 0; mt < 2; mt++)
        #pragma unroll
        for (int h = 0; h < 2; h++) {
            int row = row0 + warp_m * 32 + mt * 16 + h * 8 + tr;
            #pragma unroll
            for (int nt = 0; nt < 8; nt++) {
                int colL = warp_n * 64 + nt * 8 + tc;
                float d0 = fmaf(-2.0f, acc[mt][nt][h * 2 + 0], s_sqr[colL]);
                float d1 = fmaf(-2.0f, acc[mt][nt][h * 2 + 1], s_sqr[colL + 1]);
                __half2 hd;
                hd.x = __float2half_rn(d0);
                hd.y = __float2half_rn(d1);
                *reinterpret_cast<__half2*>(g_dist + (size_t)row * KCB + code0 + colL) = hd;
            }
        }
}

// ===========================================================================
// Refine + fused scatter
__global__ __launch_bounds__(256) void k_refine(
    const float* __restrict__ cb, float* __restrict__ out)
{
    __shared__ float s_z[DEMB];
    __shared__ float s_red[256];
    __shared__ int   s_cand[64];
    __shared__ int   s_ncand;
    __shared__ unsigned long long s_best;

    const int row = blockIdx.x;
    const int t = threadIdx.x;
    const int wid = t >> 5, lane = t & 31;

    float zval = g_z[(size_t)row * DEMB + t];
    s_z[t] = zval;
    if (t == 0) { s_ncand = 0; s_best = 0xFFFFFFFFFFFFFFFFull; }

    const __half2* drow = reinterpret_cast<const __half2*>(g_dist + (size_t)row * KCB);
    __half2 p0 = drow[t];
    __half2 p1 = drow[256 + t];
    float dt[4];
    int   ci[4];
    dt[0] = __half2float(p0.x); ci[0] = 2 * t;
    dt[1] = __half2float(p0.y); ci[1] = 2 * t + 1;
    dt[2] = __half2float(p1.x); ci[2] = 512 + 2 * t;
    dt[3] = __half2float(p1.y); ci[3] = 512 + 2 * t + 1;
    float lm = fminf(fminf(dt[0], dt[1]), fminf(dt[2], dt[3]));

    s_red[t] = lm;
    __syncthreads();
    for (int s = 128; s > 0; s >>= 1) {
        if (t < s) s_red[t] = fminf(s_red[t], s_red[t + s]);
        __syncthreads();
    }
    const float thr = s_red[0] + MARGIN;
    __syncthreads();

    #pragma unroll
    for (int i = 0; i < 4; i++) {
        if (dt[i] <= thr) {
            int idx = atomicAdd(&s_ncand, 1);
            if (idx < 64) s_cand[idx] = ci[i];
        }
    }
    __syncthreads();
    const int nc = s_ncand;

    if (nc <= 64) {
        for (int cc = wid; cc < nc; cc += 8) {
            int c = s_cand[cc];
            const float* cbr = cb + (size_t)c * DEMB;
            float dot = 0.0f;
            #pragma unroll
            for (int j = 0; j < 8; j++) dot = fmaf(s_z[lane + 32 * j], cbr[lane + 32 * j], dot);
            #pragma unroll
            for (int o = 16; o > 0; o >>= 1) dot += __shfl_xor_sync(0xffffffffu, dot, o);
            if (lane == 0) {
                float d = fmaf(-2.0f, dot, g_sqr[c]);
                unsigned u = __float_as_uint(d);
                u = (u & 0x80000000u) ? ~u : (u | 0x80000000u);
                atomicMin(&s_best, ((unsigned long long)u << 32) | (unsigned)c);
            }
        }
    } else {
        for (int c = wid; c < KCB; c += 8) {
            const float* cbr = cb + (size_t)c * DEMB;
            float dot = 0.0f;
            #pragma unroll
            for (int j = 0; j < 8; j++) dot = fmaf(s_z[lane + 32 * j], cbr[lane + 32 * j], dot);
            #pragma unroll
            for (int o = 16; o > 0; o >>= 1) dot += __shfl_xor_sync(0xffffffffu, dot, o);
            if (lane == 0) {
                float d = fmaf(-2.0f, dot, g_sqr[c]);
                unsigned u = __float_as_uint(d);
                u = (u & 0x80000000u) ? ~u : (u | 0x80000000u);
                atomicMin(&s_best, ((unsigned long long)u << 32) | (unsigned)c);
            }
        }
    }
    __syncthreads();

    unsigned long long p = s_best;
    int code = (int)(unsigned)(p & 0xFFFFFFFFull);
    unsigned ue = (unsigned)(p >> 32);
    float dmin = (ue & 0x80000000u) ? __uint_as_float(ue & 0x7FFFFFFFu)
                                    : __uint_as_float(~ue);

    atomicAdd(&g_upd[(size_t)code * DEMB + t], zval);
    float sq = zval * zval;
    #pragma unroll
    for (int o = 16; o > 0; o >>= 1) sq += __shfl_xor_sync(0xffffffffu, sq, o);
    if (lane == 0) s_red[wid] = sq;
    __syncthreads();
    if (t == 0) {
        float tot = 0.0f;
        #pragma unroll
        for (int w = 0; w < 8; w++) tot += s_red[w];
        g_codes[row] = code;
        g_dmin[row]  = dmin;
        out[OFF_CODES + row] = (float)code;
        atomicAdd(&g_loss, tot + dmin);
        atomicAdd(&g_cnt[code], 1.0f);
    }
}

// ===========================================================================
// elementwise fp32 -> fp16 hi/lo split (float4 per thread) — codebook only now
__global__ void k_split16(const float* __restrict__ src, __half* __restrict__ hi,
                          __half* __restrict__ lo) {
    size_t i = ((size_t)blockIdx.x * blockDim.x + threadIdx.x) * 4;
    float4 v = *reinterpret_cast<const float4*>(src + i);
    __half hx = __float2half_rn(v.x), hy = __float2half_rn(v.y);
    __half hz = __float2half_rn(v.z), hw = __float2half_rn(v.w);
    __half lx = __float2half_rn(v.x - __half2float(hx));
    __half ly = __float2half_rn(v.y - __half2float(hy));
    __half lz = __float2half_rn(v.z - __half2float(hz));
    __half lw = __float2half_rn(v.w - __half2float(hw));
    __half2 h01 = __halves2half2(hx, hy), h23 = __halves2half2(hz, hw);
    __half2 l01 = __halves2half2(lx, ly), l23 = __halves2half2(lz, lw);
    uint2 hp, lp;
    hp.x = *reinterpret_cast<uint32_t*>(&h01); hp.y = *reinterpret_cast<uint32_t*>(&h23);
    lp.x = *reinterpret_cast<uint32_t*>(&l01); lp.y = *reinterpret_cast<uint32_t*>(&l23);
    *reinterpret_cast<uint2*>(hi + i) = hp;
    *reinterpret_cast<uint2*>(lo + i) = lp;
}

// transpose + fp16 hi/lo split: dst[C,R] = split(src[R,C]^T)
__global__ void k_trsplit16(const float* __restrict__ src, __half* __restrict__ hi,
                            __half* __restrict__ lo, int R, int C) {
    int id = blockIdx.x * blockDim.x + threadIdx.x;
    int c = id / R, r = id - c * R;
    float v = src[(size_t)r * C + c];
    __half h = __float2half_rn(v);
    hi[id] = h;
    lo[id] = __float2half_rn(v - __half2float(h));
}

// codebook -> bf16 (hi only, for cov)
__global__ void k_convcb(const float* __restrict__ src, __nv_bfloat16* __restrict__ hi) {
    size_t i = ((size_t)blockIdx.x * blockDim.x + threadIdx.x) * 4;
    float4 v = *reinterpret_cast<const float4*>(src + i);
    __nv_bfloat162 h01 = __floats2bfloat162_rn(v.x, v.y);
    __nv_bfloat162 h23 = __floats2bfloat162_rn(v.z, v.w);
    uint2 hp;
    hp.x = *reinterpret_cast<uint32_t*>(&h01); hp.y = *reinterpret_cast<uint32_t*>(&h23);
    *reinterpret_cast<uint2*>(hi + i) = hp;
}

// ---------------------------------------------------------------------------
__global__ void k_init() {
    int i = blockIdx.x * blockDim.x + threadIdx.x;
    if (i < KCB * DEMB) g_upd[i] = 0.0f;
    if (i < KCB)        g_cnt[i] = 0.0f;
    if (i == 0)         g_loss  = 0.0f;
}

__global__ void k_sqr(const float* __restrict__ cb) {
    int k = blockIdx.x, j = threadIdx.x;
    float v = cb[k * DEMB + j];
    float s = v * v;
    #pragma unroll
    for (int o = 16; o > 0; o >>= 1) s += __shfl_xor_sync(0xffffffffu, s, o);
    __shared__ float wsum[8];
    if ((j & 31) == 0) wsum[j >> 5] = s;
    __syncthreads();
    if (j == 0) {
        float tot = 0.0f;
        #pragma unroll
        for (int w = 0; w < 8; w++) tot += wsum[w];
        g_sqr[k] = tot;
    }
}

__global__ __launch_bounds__(1024) void k_final_small(
    const float* __restrict__ ema_size_in, float* __restrict__ out)
{
    __shared__ float sh[1024];
    int t = threadIdx.x;
    float cnt = g_cnt[t];
    float esz = ema_size_in[t] + ALPHA * (cnt - ema_size_in[t]);
    out[OFF_EMA_SIZE + t] = esz;

    sh[t] = esz;
    __syncthreads();
    for (int s = 512; s > 0; s >>= 1) {
        if (t < s) sh[t] += sh[t + s];
        __syncthreads();
    }
    float n = sh[0];
    __syncthreads();

    float coef = n / (n + (float)KCB * EPSV);
    g_size[t]  = coef * (esz + EPSV);

    float p = cnt * (1.0f / (float)NROWS);
    float e = (cnt > 0.0f) ? (-p * logf(p)) : 0.0f;
    sh[t] = e;
    __syncthreads();
    for (int s = 512; s > 0; s >>= 1) {
        if (t < s) sh[t] += sh[t + s];
        __syncthreads();
    }
    if (t == 0) {
        out[OFF_ENT]    = sh[0] / logf(2.0f);
        out[OFF_EMB]    = g_loss;
        out[OFF_COMMIT] = g_loss;
    }
}

__global__ void k_ema(const float* __restrict__ ema_vecs_in, float* __restrict__ out) {
    int i = blockIdx.x * blockDim.x + threadIdx.x;
    float v = ema_vecs_in[i] + ALPHA * (g_upd[i] - ema_vecs_in[i]);
    out[OFF_EMA_VECS + i] = v;
    out[OFF_WEIGHT + i]   = v / g_size[i >> 8];
}

__global__ __launch_bounds__(256) void k_gather(float* __restrict__ out) {
    int row  = blockIdx.x;
    int code = g_codes[row];
    const float4* src = reinterpret_cast<const float4*>(g_Y + (size_t)code * DIN);
    float4* dst = reinterpret_cast<float4*>(out + OFF_X + (size_t)row * DIN);
    dst[threadIdx.x] = src[threadIdx.x];
}

// ---------------------------------------------------------------------------
extern "C" void kernel_launch(void* const* d_in, const int* in_sizes, int n_in,
                              void* d_out, int out_size) {
    const float* input    = (const float*)d_in[0];
    const float* W_send   = (const float*)d_in[1];
    const float* b_send   = (const float*)d_in[2];
    const float* W_recv   = (const float*)d_in[3];
    const float* b_recv   = (const float*)d_in[4];
    const float* codebook = (const float*)d_in[5];
    const float* ema_vecs = (const float*)d_in[6];
    const float* ema_size = (const float*)d_in[7];
    float* out = (float*)d_out;

    float *z_ptr, *Y_ptr;
    __half *wsh, *wsl, *wrh, *wrl, *cb16h, *cb16l;
    __nv_bfloat16 *zh, *cbh;
    cudaGetSymbolAddress((void**)&z_ptr, g_z);
    cudaGetSymbolAddress((void**)&Y_ptr, g_Y);
    cudaGetSymbolAddress((void**)&wsh, g_wsh);   cudaGetSymbolAddress((void**)&wsl, g_wsl);
    cudaGetSymbolAddress((void**)&wrh, g_wrh);   cudaGetSymbolAddress((void**)&wrl, g_wrl);
    cudaGetSymbolAddress((void**)&cb16h, g_cbh16); cudaGetSymbolAddress((void**)&cb16l, g_cbl16);
    cudaGetSymbolAddress((void**)&zh, g_zh);
    cudaGetSymbolAddress((void**)&cbh, g_cbh);

    // one-time host-side setup (no device memory involved)
    static cudaStream_t s1 = nullptr, s2 = nullptr;
    static cudaEvent_t eFork = nullptr, eJoin2 = nullptr, eEnd = nullptr;
    if (!s1) {
        cudaStreamCreateWithFlags(&s1, cudaStreamNonBlocking);
        cudaStreamCreateWithFlags(&s2, cudaStreamNonBlocking);
        cudaEventCreateWithFlags(&eFork,  cudaEventDisableTiming);
        cudaEventCreateWithFlags(&eJoin2, cudaEventDisableTiming);
        cudaEventCreateWithFlags(&eEnd,   cudaEventDisableTiming);
        cudaFuncSetAttribute(k_zgemm, cudaFuncAttributeMaxDynamicSharedMemorySize, HSMEM_BYTES);
        cudaFuncSetAttribute(k_hgemm, cudaFuncAttributeMaxDynamicSharedMemorySize, HSMEM_BYTES);
    }

    // fork both worker streams off the capture/default stream
    cudaEventRecord(eFork, 0);
    cudaStreamWaitEvent(s1, eFork, 0);
    cudaStreamWaitEvent(s2, eFork, 0);

    // s1: z chain
    k_trsplit16<<<DIN * DEMB / 256, 256, 0, s1>>>(W_send, wsh, wsl, DIN, DEMB);
    k_zgemm<<<dim3(2, 128), 256, HSMEM_BYTES, s1>>>(input, wsh, wsl, b_send,
                                                    z_ptr, zh, DEMB, DIN);

    // s2: independent prep + Y
    k_init<<<1024, 256, 0, s2>>>();
    k_sqr<<<KCB, 256, 0, s2>>>(codebook);
    k_convcb<<<KCB * DEMB / 1024, 256, 0, s2>>>(codebook, cbh);
    k_trsplit16<<<DIN * DEMB / 256, 256, 0, s2>>>(W_recv, wrh, wrl, DEMB, DIN);
    k_split16<<<KCB * DEMB / 1024, 256, 0, s2>>>(codebook, cb16h, cb16l);
    k_hgemm<<<dim3(8, 8), 256, HSMEM_BYTES, s2>>>(cb16h, cb16l, wrh, wrl, b_recv,
                                                  Y_ptr, DIN, DEMB);
    cudaEventRecord(eJoin2, s2);

    // join: cov needs zh (s1) + cbh/sqr (s2)
    cudaStreamWaitEvent(s1, eJoin2, 0);
    k_cov<<<dim3(8, 128), 256, 0, s1>>>();
    k_refine<<<NROWS, 256, 0, s1>>>(codebook, out);
    k_final_small<<<1, 1024, 0, s1>>>(ema_size, out);
    k_ema<<<1024, 256, 0, s1>>>(ema_vecs, out);
    k_gather<<<NROWS, 256, 0, s1>>>(out);

    // join back to the default/capture stream
    cudaEventRecord(eEnd, s1);
    cudaStreamWaitEvent(0, eEnd, 0);
}